// round 1
// baseline (speedup 1.0000x reference)
#include <cuda_runtime.h>
#include <cuda_bf16.h>
#include <math.h>

// Problem constants
#define B 2
#define C 128
#define H 128
#define W 128
#define HP 130
#define WP 130
#define NPT 9          // kernel points
#define CO 128

// Scratch (device globals; allocation-free)
__device__ __align__(16) float g_xp[B * HP * WP * C];          // padded NHWC x   (~17.3 MB)
__device__ __align__(16) float g_gates[B * H * W * NPT * 4];   // modulated bilinear gates (4.7 MB)
__device__ __align__(16) int   g_offs [B * H * W * NPT * 4];   // corner spatial offsets   (4.7 MB)
__device__ __align__(16) float g_wpm[C * NPT * 27];            // offset/mask weights, [k=ci*9+tap][ch]
__device__ __align__(16) float g_wc [C * NPT * CO];            // main conv weights,  [k=ci*9+n][co]

// ---------------------------------------------------------------------------
// Kernel 0: zero padded buffer (borders must be 0; interior overwritten later)
__global__ void zero_xp_kernel() {
    const int total = B * HP * WP * C / 4;
    float4* p = reinterpret_cast<float4*>(g_xp);
    float4 z = make_float4(0.f, 0.f, 0.f, 0.f);
    for (int i = blockIdx.x * blockDim.x + threadIdx.x; i < total; i += gridDim.x * blockDim.x)
        p[i] = z;
}

// ---------------------------------------------------------------------------
// Kernel 1: weight re-layout
//   g_wpm[(ci*9+tap)*27 + ch] = ch<18 ? w_p[ch][ci][tap] : w_m[ch-18][ci][tap]
//   g_wc [(ci*9+n)*128 + co]  = w_conv[co][ci][n]
__global__ void prep_weights_kernel(const float* __restrict__ wp,
                                    const float* __restrict__ wm,
                                    const float* __restrict__ wc) {
    const int n_pm = C * NPT * 27;       // 31104
    const int n_wc = C * NPT * CO;       // 147456
    for (int e = blockIdx.x * blockDim.x + threadIdx.x; e < n_pm + n_wc;
         e += gridDim.x * blockDim.x) {
        if (e < n_pm) {
            int k = e / 27, ch = e - k * 27;
            int ci = k / 9, tap = k - ci * 9;
            float v = (ch < 18) ? wp[(ch * C + ci) * 9 + tap]
                                : wm[((ch - 18) * C + ci) * 9 + tap];
            g_wpm[e] = v;
        } else {
            int e2 = e - n_pm;
            int k = e2 >> 7, co = e2 & 127;
            int ci = k / 9, n = k - ci * 9;
            g_wc[e2] = wc[(co * C + ci) * 9 + n];
        }
    }
}

// ---------------------------------------------------------------------------
// Kernel 2: pad + transpose NCHW -> padded NHWC
__global__ void pad_transpose_kernel(const float* __restrict__ x) {
    __shared__ float tile[32][33];
    int w0 = blockIdx.x * 32;
    int c0 = blockIdx.y * 32;
    int bh = blockIdx.z;
    int b = bh >> 7, h = bh & 127;
    int tx = threadIdx.x, ty = threadIdx.y;
#pragma unroll
    for (int r = 0; r < 4; ++r) {
        int ci = c0 + ty + r * 8;
        tile[ty + r * 8][tx] = x[(((size_t)b * C + ci) * H + h) * W + w0 + tx];
    }
    __syncthreads();
#pragma unroll
    for (int r = 0; r < 4; ++r) {
        int w = w0 + ty + r * 8;
        g_xp[(((size_t)b * HP + h + 1) * WP + (w + 1)) * C + c0 + tx] = tile[tx][ty + r * 8];
    }
}

// ---------------------------------------------------------------------------
// Kernel 3: offset/mask 3x3 conv (27 channels) + bilinear gate/index precompute
// 256 blocks (b*H), 128 threads (one per w).
__global__ __launch_bounds__(128) void offset_kernel(const float* __restrict__ bp,
                                                     const float* __restrict__ bm) {
    __shared__ float ws[72 * 27];  // 8-ci chunk of weights
    int b = blockIdx.x >> 7, h = blockIdx.x & 127;
    int w = threadIdx.x;

    float acc[27];
#pragma unroll
    for (int ch = 0; ch < 18; ++ch) acc[ch] = bp[ch];
#pragma unroll
    for (int ch = 0; ch < 9; ++ch) acc[18 + ch] = bm[ch];

    for (int ci0 = 0; ci0 < C; ci0 += 8) {
        __syncthreads();
        for (int i = threadIdx.x; i < 72 * 27; i += 128)
            ws[i] = g_wpm[ci0 * 9 * 27 + i];
        __syncthreads();
#pragma unroll
        for (int dh = 0; dh < 3; ++dh) {
#pragma unroll
            for (int dw = 0; dw < 3; ++dw) {
                const float* xp = g_xp + (((size_t)b * HP + h + dh) * WP + (w + dw)) * C + ci0;
                float4 v0 = *reinterpret_cast<const float4*>(xp);
                float4 v1 = *reinterpret_cast<const float4*>(xp + 4);
                float xv[8] = {v0.x, v0.y, v0.z, v0.w, v1.x, v1.y, v1.z, v1.w};
                int tap = dh * 3 + dw;
#pragma unroll
                for (int j = 0; j < 8; ++j) {
                    const float* wrow = ws + (j * 9 + tap) * 27;
                    float xvj = xv[j];
#pragma unroll
                    for (int ch = 0; ch < 27; ++ch)
                        acc[ch] = fmaf(xvj, wrow[ch], acc[ch]);
                }
            }
        }
    }

    int pix = h * W + w;
    size_t base = (size_t)(b * (H * W) + pix) * 36;
#pragma unroll
    for (int n = 0; n < NPT; ++n) {
        float m = 1.f / (1.f + expf(-acc[18 + n]));
        float px = acc[n]     + (float)(h + 1) + (float)(n / 3 - 1);
        float py = acc[9 + n] + (float)(w + 1) + (float)(n % 3 - 1);
        float fx = floorf(px), fy = floorf(py);
        float qltx = fminf(fmaxf(fx,       0.f), 129.f);
        float qlty = fminf(fmaxf(fy,       0.f), 129.f);
        float qrbx = fminf(fmaxf(fx + 1.f, 0.f), 129.f);
        float qrby = fminf(fmaxf(fy + 1.f, 0.f), 129.f);
        float pxc = fminf(fmaxf(px, 0.f), 129.f);
        float pyc = fminf(fmaxf(py, 0.f), 129.f);
        float ax = 1.f + (qltx - pxc);
        float bx = 1.f - (qrbx - pxc);
        float ay = 1.f + (qlty - pyc);
        float by = 1.f - (qrby - pyc);
        int ilt_x = (int)qltx, ilt_y = (int)qlty;
        int irb_x = (int)qrbx, irb_y = (int)qrby;
        g_gates[base + n * 4 + 0] = ax * ay * m;   // lt
        g_gates[base + n * 4 + 1] = bx * by * m;   // rb
        g_gates[base + n * 4 + 2] = ax * by * m;   // lb
        g_gates[base + n * 4 + 3] = bx * ay * m;   // rt
        g_offs [base + n * 4 + 0] = ilt_x * WP + ilt_y;
        g_offs [base + n * 4 + 1] = irb_x * WP + irb_y;
        g_offs [base + n * 4 + 2] = ilt_x * WP + irb_y;
        g_offs [base + n * 4 + 3] = irb_x * WP + ilt_y;
    }
}

// ---------------------------------------------------------------------------
// Kernel 4: fused bilinear gather + GEMM.
// Block: 32 pixels (row segment) x all 128 co. 256 threads, 16 acc/thread.
// K = 1152 chunked by 16 ci (Kc = 144).
#define TP 32
#define KC 144
#define U_STRIDE 145
__global__ __launch_bounds__(256) void main_kernel(float* __restrict__ out) {
    extern __shared__ float smem[];
    float* w_s  = smem;                         // 144*128 = 18432 floats
    float* u_s  = smem + 18432;                 // 32*145  = 4640 floats
    float* gt_s = u_s + TP * U_STRIDE;          // 1152 floats
    int*   of_s = reinterpret_cast<int*>(gt_s + TP * 36);  // 1152 ints

    int tid = threadIdx.x;
    int b = blockIdx.z, h = blockIdx.y, w0 = blockIdx.x * TP;
    int pix0 = h * W + w0;

    // preload gates / offsets for the 32 pixels
    {
        const float* gsrc = g_gates + (size_t)(b * (H * W) + pix0) * 36;
        const int*   osrc = g_offs  + (size_t)(b * (H * W) + pix0) * 36;
        for (int i = tid; i < TP * 36; i += 256) {
            gt_s[i] = gsrc[i];
            of_s[i] = osrc[i];
        }
    }

    const float4* xb4 = reinterpret_cast<const float4*>(g_xp) + (size_t)b * HP * WP * (C / 4);

    int tx = tid & 31;        // pixel
    int ty = tid >> 5;        // co group (0..7)
    int co0 = ty * 16;

    float acc[16];
#pragma unroll
    for (int j = 0; j < 16; ++j) acc[j] = 0.f;

    for (int chunk = 0; chunk < 8; ++chunk) {
        __syncthreads();   // prior FMA done; safe to overwrite w_s/u_s (also covers gate preload)

        // load weight chunk (144 x 128)
        {
            const float4* wsrc = reinterpret_cast<const float4*>(g_wc) + chunk * 4608;
            float4* wdst = reinterpret_cast<float4*>(w_s);
#pragma unroll
            for (int i = 0; i < 18; ++i)
                wdst[tid + i * 256] = wsrc[tid + i * 256];
        }

        // build u tile: 32 pixels x 16 ci x 9 n (as 4-ci quads)
        int ci0q = chunk * 4;  // float4 index of first ci in chunk
        for (int i = tid; i < TP * 36; i += 256) {
            int pix = i / 36;
            int rr = i - pix * 36;
            int n = rr >> 2, q = rr & 3;
            int gidx = pix * 36 + n * 4;
            float g0 = gt_s[gidx + 0], g1 = gt_s[gidx + 1];
            float g2 = gt_s[gidx + 2], g3 = gt_s[gidx + 3];
            int o0 = of_s[gidx + 0], o1 = of_s[gidx + 1];
            int o2 = of_s[gidx + 2], o3 = of_s[gidx + 3];
            int cb = ci0q + q;
            float4 v0 = xb4[o0 * 32 + cb];
            float4 v1 = xb4[o1 * 32 + cb];
            float4 v2 = xb4[o2 * 32 + cb];
            float4 v3 = xb4[o3 * 32 + cb];
            float* ud = u_s + pix * U_STRIDE + q * 36 + n;
            ud[0]  = fmaf(g3, v3.x, fmaf(g2, v2.x, fmaf(g1, v1.x, g0 * v0.x)));
            ud[9]  = fmaf(g3, v3.y, fmaf(g2, v2.y, fmaf(g1, v1.y, g0 * v0.y)));
            ud[18] = fmaf(g3, v3.z, fmaf(g2, v2.z, fmaf(g1, v1.z, g0 * v0.z)));
            ud[27] = fmaf(g3, v3.w, fmaf(g2, v2.w, fmaf(g1, v1.w, g0 * v0.w)));
        }
        __syncthreads();

        // GEMM: acc[co0..co0+15] += w_s[k][co] * u_s[pix][k]
        const float* up = u_s + tx * U_STRIDE;
#pragma unroll 2
        for (int k = 0; k < KC; ++k) {
            float uv = up[k];
            const float4* wr = reinterpret_cast<const float4*>(w_s + k * 128 + co0);
            float4 wa = wr[0], wb = wr[1], wc2 = wr[2], wd = wr[3];
            acc[0]  = fmaf(uv, wa.x,  acc[0]);
            acc[1]  = fmaf(uv, wa.y,  acc[1]);
            acc[2]  = fmaf(uv, wa.z,  acc[2]);
            acc[3]  = fmaf(uv, wa.w,  acc[3]);
            acc[4]  = fmaf(uv, wb.x,  acc[4]);
            acc[5]  = fmaf(uv, wb.y,  acc[5]);
            acc[6]  = fmaf(uv, wb.z,  acc[6]);
            acc[7]  = fmaf(uv, wb.w,  acc[7]);
            acc[8]  = fmaf(uv, wc2.x, acc[8]);
            acc[9]  = fmaf(uv, wc2.y, acc[9]);
            acc[10] = fmaf(uv, wc2.z, acc[10]);
            acc[11] = fmaf(uv, wc2.w, acc[11]);
            acc[12] = fmaf(uv, wd.x,  acc[12]);
            acc[13] = fmaf(uv, wd.y,  acc[13]);
            acc[14] = fmaf(uv, wd.z,  acc[14]);
            acc[15] = fmaf(uv, wd.w,  acc[15]);
        }
    }

#pragma unroll
    for (int j = 0; j < 16; ++j) {
        int co = co0 + j;
        out[(((size_t)b * CO + co) * H + h) * W + w0 + tx] = acc[j];
    }
}

// ---------------------------------------------------------------------------
extern "C" void kernel_launch(void* const* d_in, const int* in_sizes, int n_in,
                              void* d_out, int out_size) {
    const float* x      = (const float*)d_in[0];
    const float* w_p    = (const float*)d_in[1];
    const float* b_p    = (const float*)d_in[2];
    const float* w_m    = (const float*)d_in[3];
    const float* b_m    = (const float*)d_in[4];
    const float* w_conv = (const float*)d_in[5];
    float* out = (float*)d_out;

    static const int kMainSmem = (18432 + TP * U_STRIDE + TP * 36 * 2) * 4;  // 101504 B
    cudaFuncSetAttribute(main_kernel, cudaFuncAttributeMaxDynamicSharedMemorySize, kMainSmem);

    zero_xp_kernel<<<1024, 256>>>();
    prep_weights_kernel<<<698, 256>>>(w_p, w_m, w_conv);
    pad_transpose_kernel<<<dim3(W / 32, C / 32, B * H), dim3(32, 8)>>>(x);
    offset_kernel<<<B * H, 128>>>(b_p, b_m);
    main_kernel<<<dim3(W / TP, H, B), 256, kMainSmem>>>(out);
}

// round 2
// speedup vs baseline: 1.1546x; 1.1546x over previous
#include <cuda_runtime.h>
#include <cuda_bf16.h>
#include <math.h>

// Problem constants
#define B 2
#define C 128
#define H 128
#define W 128
#define HP 130
#define WP 130
#define NPT 9
#define CO 128

// Scratch (device globals; allocation-free)
__device__ __align__(16) float g_xp[B * HP * WP * C];          // padded NHWC x (~17.3 MB)
__device__ __align__(16) float g_gates[B * H * W * NPT * 4];   // modulated bilinear gates
__device__ __align__(16) int   g_offs [B * H * W * NPT * 4];   // corner spatial offsets
__device__ __align__(16) float g_wpm[C * NPT * 27];            // offset/mask weights [k=ci*9+tap][ch]
__device__ __align__(16) float g_wc [C * NPT * CO];            // main conv weights [k=ci*9+n][co]
__device__ __align__(16) float g_part[4 * 27 * B * H * W];     // split-K partials (14.2 MB)

// ---------------------------------------------------------------------------
// Kernel 0: zero padded buffer
__global__ void zero_xp_kernel() {
    const int total = B * HP * WP * C / 4;
    float4* p = reinterpret_cast<float4*>(g_xp);
    float4 z = make_float4(0.f, 0.f, 0.f, 0.f);
    for (int i = blockIdx.x * blockDim.x + threadIdx.x; i < total; i += gridDim.x * blockDim.x)
        p[i] = z;
}

// ---------------------------------------------------------------------------
// Kernel 1: weight re-layout
__global__ void prep_weights_kernel(const float* __restrict__ wp,
                                    const float* __restrict__ wm,
                                    const float* __restrict__ wc) {
    const int n_pm = C * NPT * 27;       // 31104
    const int n_wc = C * NPT * CO;       // 147456
    for (int e = blockIdx.x * blockDim.x + threadIdx.x; e < n_pm + n_wc;
         e += gridDim.x * blockDim.x) {
        if (e < n_pm) {
            int k = e / 27, ch = e - k * 27;
            int ci = k / 9, tap = k - ci * 9;
            float v = (ch < 18) ? wp[(ch * C + ci) * 9 + tap]
                                : wm[((ch - 18) * C + ci) * 9 + tap];
            g_wpm[e] = v;
        } else {
            int e2 = e - n_pm;
            int k = e2 >> 7, co = e2 & 127;
            int ci = k / 9, n = k - ci * 9;
            g_wc[e2] = wc[(co * C + ci) * 9 + n];
        }
    }
}

// ---------------------------------------------------------------------------
// Kernel 2: pad + transpose NCHW -> padded NHWC
__global__ void pad_transpose_kernel(const float* __restrict__ x) {
    __shared__ float tile[32][33];
    int w0 = blockIdx.x * 32;
    int c0 = blockIdx.y * 32;
    int bh = blockIdx.z;
    int b = bh >> 7, h = bh & 127;
    int tx = threadIdx.x, ty = threadIdx.y;
#pragma unroll
    for (int r = 0; r < 4; ++r) {
        int ci = c0 + ty + r * 8;
        tile[ty + r * 8][tx] = x[(((size_t)b * C + ci) * H + h) * W + w0 + tx];
    }
    __syncthreads();
#pragma unroll
    for (int r = 0; r < 4; ++r) {
        int w = w0 + ty + r * 8;
        g_xp[(((size_t)b * HP + h + 1) * WP + (w + 1)) * C + c0 + tx] = tile[tx][ty + r * 8];
    }
}

// ---------------------------------------------------------------------------
// Kernel 3a: offset/mask conv, split-K x4. Block = (slab of 32 ci, one row).
// x rows staged in smem transposed [ci][w] -> single L1 read per value.
__global__ __launch_bounds__(128) void off_part_kernel() {
    __shared__ float ws8[8 * 9 * 27];       // 1944 floats
    __shared__ float xs[3 * 8 * 131];       // 3 rows x 8 ci x 131 w (transposed)
    int s = blockIdx.x;                      // slab 0..3
    int bh = blockIdx.y;                     // 0..255
    int b = bh >> 7, h = bh & 127;
    int tx = threadIdx.x;

    float acc[27];
#pragma unroll
    for (int ch = 0; ch < 27; ++ch) acc[ch] = 0.f;

    const float4* xp4 = reinterpret_cast<const float4*>(g_xp);

    for (int c8 = 0; c8 < 4; ++c8) {
        __syncthreads();
        // stage 8-ci weight slice
        {
            const float* wsrc = g_wpm + (s * 32 + c8 * 8) * 9 * 27;
            for (int i = tx; i < 1944; i += 128) ws8[i] = wsrc[i];
        }
        // stage x: 3 rows x 130 w x 8 ci, transposed to [row][ci][w]
        for (int i = tx; i < 780; i += 128) {
            int dh = i / 260;
            int r = i - dh * 260;
            int wq = r >> 1;
            int cq = r & 1;
            float4 v = xp4[(((size_t)b * HP + h + dh) * WP + wq) * 32 + s * 8 + c8 * 2 + cq];
            float* xd = xs + (dh * 8 + cq * 4) * 131 + wq;
            xd[0]   = v.x;
            xd[131] = v.y;
            xd[262] = v.z;
            xd[393] = v.w;
        }
        __syncthreads();
#pragma unroll
        for (int dh = 0; dh < 3; ++dh) {
#pragma unroll
            for (int dw = 0; dw < 3; ++dw) {
                int tap = dh * 3 + dw;
#pragma unroll
                for (int j = 0; j < 8; ++j) {
                    float xvj = xs[(dh * 8 + j) * 131 + tx + dw];
                    const float* wrow = ws8 + (j * 9 + tap) * 27;
#pragma unroll
                    for (int ch = 0; ch < 27; ++ch)
                        acc[ch] = fmaf(xvj, wrow[ch], acc[ch]);
                }
            }
        }
    }
    int pix = bh * 128 + tx;
#pragma unroll
    for (int ch = 0; ch < 27; ++ch)
        g_part[(s * 27 + ch) * (B * H * W) + pix] = acc[ch];
}

// ---------------------------------------------------------------------------
// Kernel 3b: combine partials + bias, sigmoid, bilinear gate/index precompute.
__global__ __launch_bounds__(128) void off_comb_kernel(const float* __restrict__ bp,
                                                       const float* __restrict__ bm) {
    int bh = blockIdx.x;
    int b = bh >> 7, h = bh & 127;
    int w = threadIdx.x;
    int pix = bh * 128 + w;

    float acc[27];
#pragma unroll
    for (int ch = 0; ch < 18; ++ch) acc[ch] = bp[ch];
#pragma unroll
    for (int ch = 0; ch < 9; ++ch) acc[18 + ch] = bm[ch];
#pragma unroll
    for (int s = 0; s < 4; ++s)
#pragma unroll
        for (int ch = 0; ch < 27; ++ch)
            acc[ch] += g_part[(s * 27 + ch) * (B * H * W) + pix];

    size_t base = (size_t)pix * 36;
#pragma unroll
    for (int n = 0; n < NPT; ++n) {
        float m = 1.f / (1.f + expf(-acc[18 + n]));
        float px = acc[n]     + (float)(h + 1) + (float)(n / 3 - 1);
        float py = acc[9 + n] + (float)(w + 1) + (float)(n % 3 - 1);
        float fx = floorf(px), fy = floorf(py);
        float qltx = fminf(fmaxf(fx,       0.f), 129.f);
        float qlty = fminf(fmaxf(fy,       0.f), 129.f);
        float qrbx = fminf(fmaxf(fx + 1.f, 0.f), 129.f);
        float qrby = fminf(fmaxf(fy + 1.f, 0.f), 129.f);
        float pxc = fminf(fmaxf(px, 0.f), 129.f);
        float pyc = fminf(fmaxf(py, 0.f), 129.f);
        float ax = 1.f + (qltx - pxc);
        float bx = 1.f - (qrbx - pxc);
        float ay = 1.f + (qlty - pyc);
        float by = 1.f - (qrby - pyc);
        int ilt_x = (int)qltx, ilt_y = (int)qlty;
        int irb_x = (int)qrbx, irb_y = (int)qrby;
        g_gates[base + n * 4 + 0] = ax * ay * m;
        g_gates[base + n * 4 + 1] = bx * by * m;
        g_gates[base + n * 4 + 2] = ax * by * m;
        g_gates[base + n * 4 + 3] = bx * ay * m;
        g_offs [base + n * 4 + 0] = ilt_x * WP + ilt_y;
        g_offs [base + n * 4 + 1] = irb_x * WP + irb_y;
        g_offs [base + n * 4 + 2] = ilt_x * WP + irb_y;
        g_offs [base + n * 4 + 3] = irb_x * WP + ilt_y;
    }
}

// ---------------------------------------------------------------------------
// Kernel 4: fused bilinear gather + GEMM.
// Block: 64 pixels x 128 co, 256 threads, 2 pixels x 16 co per thread.
// K = 1152 chunked by 8 ci (KC2 = 72). smem 74 KB -> 2 blocks/SM.
#define TPX 64
#define KC2 72
#define USTR 66
__global__ __launch_bounds__(256, 2) void main_kernel(float* __restrict__ out) {
    extern __shared__ float smem[];
    float* w_s  = smem;                         // 72*128 = 9216 floats
    float* u_s  = smem + 9216;                  // 72*66  = 4752 floats
    float* gt_s = u_s + KC2 * USTR;             // 64*36  = 2304 floats
    int*   of_s = reinterpret_cast<int*>(gt_s + TPX * 36);  // 2304 ints

    int tid = threadIdx.x;
    int b = blockIdx.z, h = blockIdx.y, w0 = blockIdx.x * TPX;
    int pix0 = h * W + w0;

    {
        const float* gsrc = g_gates + (size_t)(b * (H * W) + pix0) * 36;
        const int*   osrc = g_offs  + (size_t)(b * (H * W) + pix0) * 36;
        for (int i = tid; i < TPX * 36; i += 256) {
            gt_s[i] = gsrc[i];
            of_s[i] = osrc[i];
        }
    }

    const float4* xb4 = reinterpret_cast<const float4*>(g_xp) + (size_t)b * HP * WP * 32;

    int p = tid & 31;          // pixel pair (pixels 2p, 2p+1)
    int g = tid >> 5;          // co group
    int co0 = g * 16;

    float acc[32];
#pragma unroll
    for (int j = 0; j < 32; ++j) acc[j] = 0.f;

    for (int chunk = 0; chunk < 16; ++chunk) {
        __syncthreads();
        // weights: 72 x 128 = 2304 float4
        {
            const float4* wsrc = reinterpret_cast<const float4*>(g_wc) + chunk * 2304;
            float4* wdst = reinterpret_cast<float4*>(w_s);
#pragma unroll
            for (int i = 0; i < 9; ++i)
                wdst[tid + i * 256] = wsrc[tid + i * 256];
        }
        // gather u tile: 64 pixels x 18 (q,n) entries, layout u_s[k][pix]
        for (int i = tid; i < TPX * 18; i += 256) {
            int pix = i / 18;
            int rr = i - pix * 18;
            int q = rr / 9;
            int n = rr - q * 9;
            int gidx = pix * 36 + n * 4;
            float g0 = gt_s[gidx + 0], g1 = gt_s[gidx + 1];
            float g2 = gt_s[gidx + 2], g3 = gt_s[gidx + 3];
            int o0 = of_s[gidx + 0], o1 = of_s[gidx + 1];
            int o2 = of_s[gidx + 2], o3 = of_s[gidx + 3];
            int cb = chunk * 2 + q;
            float4 v0 = xb4[o0 * 32 + cb];
            float4 v1 = xb4[o1 * 32 + cb];
            float4 v2 = xb4[o2 * 32 + cb];
            float4 v3 = xb4[o3 * 32 + cb];
            float* ud = u_s + (q * 36 + n) * USTR + pix;
            ud[0 * 9 * USTR]  = fmaf(g3, v3.x, fmaf(g2, v2.x, fmaf(g1, v1.x, g0 * v0.x)));
            ud[1 * 9 * USTR]  = fmaf(g3, v3.y, fmaf(g2, v2.y, fmaf(g1, v1.y, g0 * v0.y)));
            ud[2 * 9 * USTR]  = fmaf(g3, v3.z, fmaf(g2, v2.z, fmaf(g1, v1.z, g0 * v0.z)));
            ud[3 * 9 * USTR]  = fmaf(g3, v3.w, fmaf(g2, v2.w, fmaf(g1, v1.w, g0 * v0.w)));
        }
        __syncthreads();

        // GEMM: 2 pixels x 16 co per thread
        const float* up  = u_s + 2 * p;
        const float* wp0 = w_s + co0;
#pragma unroll 2
        for (int k = 0; k < KC2; ++k) {
            float2 uv = *reinterpret_cast<const float2*>(up + k * USTR);
            const float4* wr = reinterpret_cast<const float4*>(wp0 + k * 128);
            float4 wa = wr[0], wb = wr[1], wc2 = wr[2], wd = wr[3];
            acc[0]  = fmaf(uv.x, wa.x,  acc[0]);   acc[16] = fmaf(uv.y, wa.x,  acc[16]);
            acc[1]  = fmaf(uv.x, wa.y,  acc[1]);   acc[17] = fmaf(uv.y, wa.y,  acc[17]);
            acc[2]  = fmaf(uv.x, wa.z,  acc[2]);   acc[18] = fmaf(uv.y, wa.z,  acc[18]);
            acc[3]  = fmaf(uv.x, wa.w,  acc[3]);   acc[19] = fmaf(uv.y, wa.w,  acc[19]);
            acc[4]  = fmaf(uv.x, wb.x,  acc[4]);   acc[20] = fmaf(uv.y, wb.x,  acc[20]);
            acc[5]  = fmaf(uv.x, wb.y,  acc[5]);   acc[21] = fmaf(uv.y, wb.y,  acc[21]);
            acc[6]  = fmaf(uv.x, wb.z,  acc[6]);   acc[22] = fmaf(uv.y, wb.z,  acc[22]);
            acc[7]  = fmaf(uv.x, wb.w,  acc[7]);   acc[23] = fmaf(uv.y, wb.w,  acc[23]);
            acc[8]  = fmaf(uv.x, wc2.x, acc[8]);   acc[24] = fmaf(uv.y, wc2.x, acc[24]);
            acc[9]  = fmaf(uv.x, wc2.y, acc[9]);   acc[25] = fmaf(uv.y, wc2.y, acc[25]);
            acc[10] = fmaf(uv.x, wc2.z, acc[10]);  acc[26] = fmaf(uv.y, wc2.z, acc[26]);
            acc[11] = fmaf(uv.x, wc2.w, acc[11]);  acc[27] = fmaf(uv.y, wc2.w, acc[27]);
            acc[12] = fmaf(uv.x, wd.x,  acc[12]);  acc[28] = fmaf(uv.y, wd.x,  acc[28]);
            acc[13] = fmaf(uv.x, wd.y,  acc[13]);  acc[29] = fmaf(uv.y, wd.y,  acc[29]);
            acc[14] = fmaf(uv.x, wd.z,  acc[14]);  acc[30] = fmaf(uv.y, wd.z,  acc[30]);
            acc[15] = fmaf(uv.x, wd.w,  acc[15]);  acc[31] = fmaf(uv.y, wd.w,  acc[31]);
        }
    }

#pragma unroll
    for (int j = 0; j < 16; ++j) {
        int co = co0 + j;
        float2 v = make_float2(acc[j], acc[16 + j]);
        *reinterpret_cast<float2*>(out + (((size_t)b * CO + co) * H + h) * W + w0 + 2 * p) = v;
    }
}

// ---------------------------------------------------------------------------
extern "C" void kernel_launch(void* const* d_in, const int* in_sizes, int n_in,
                              void* d_out, int out_size) {
    const float* x      = (const float*)d_in[0];
    const float* w_p    = (const float*)d_in[1];
    const float* b_p    = (const float*)d_in[2];
    const float* w_m    = (const float*)d_in[3];
    const float* b_m    = (const float*)d_in[4];
    const float* w_conv = (const float*)d_in[5];
    float* out = (float*)d_out;

    static const int kMainSmem = (KC2 * 128 + KC2 * USTR + TPX * 36 * 2) * 4;  // 74304 B
    cudaFuncSetAttribute(main_kernel, cudaFuncAttributeMaxDynamicSharedMemorySize, kMainSmem);

    zero_xp_kernel<<<1024, 256>>>();
    prep_weights_kernel<<<698, 256>>>(w_p, w_m, w_conv);
    pad_transpose_kernel<<<dim3(W / 32, C / 32, B * H), dim3(32, 8)>>>(x);
    off_part_kernel<<<dim3(4, B * H), 128>>>();
    off_comb_kernel<<<B * H, 128>>>(b_p, b_m);
    main_kernel<<<dim3(W / TPX, H, B), 256, kMainSmem>>>(out);
}

// round 3
// speedup vs baseline: 1.2451x; 1.0784x over previous
#include <cuda_runtime.h>
#include <cuda_bf16.h>
#include <math.h>

// Problem constants
#define B 2
#define C 128
#define H 128
#define W 128
#define HP 130
#define WP 130
#define NPT 9
#define CO 128

// Scratch (device globals; allocation-free)
__device__ __align__(16) float g_xp[B * HP * WP * C];          // padded NHWC x (~17.3 MB)
__device__ __align__(16) float g_gates[B * H * W * NPT * 4];   // modulated bilinear gates
__device__ __align__(16) int   g_offs [B * H * W * NPT * 4];   // corner spatial offsets
__device__ __align__(16) float g_wpm[C * NPT * 28];            // offset/mask weights [k=ci*9+tap][ch(28 padded)]
__device__ __align__(16) float g_wc [C * NPT * CO];            // main conv weights [k=ci*9+n][co]
__device__ __align__(16) float g_part[4 * 27 * B * H * W];     // split-K partials

// ---------------------------------------------------------------------------
// Kernel 0: zero padded buffer
__global__ void zero_xp_kernel() {
    const int total = B * HP * WP * C / 4;
    float4* p = reinterpret_cast<float4*>(g_xp);
    float4 z = make_float4(0.f, 0.f, 0.f, 0.f);
    for (int i = blockIdx.x * blockDim.x + threadIdx.x; i < total; i += gridDim.x * blockDim.x)
        p[i] = z;
}

// ---------------------------------------------------------------------------
// Kernel 1: weight re-layout (offset/mask weights padded ch 27->28)
__global__ void prep_weights_kernel(const float* __restrict__ wp,
                                    const float* __restrict__ wm,
                                    const float* __restrict__ wc) {
    const int n_pm = C * NPT * 28;       // 32256
    const int n_wc = C * NPT * CO;       // 147456
    for (int e = blockIdx.x * blockDim.x + threadIdx.x; e < n_pm + n_wc;
         e += gridDim.x * blockDim.x) {
        if (e < n_pm) {
            int k = e / 28, ch = e - k * 28;
            int ci = k / 9, tap = k - ci * 9;
            float v;
            if (ch < 18)      v = wp[(ch * C + ci) * 9 + tap];
            else if (ch < 27) v = wm[((ch - 18) * C + ci) * 9 + tap];
            else              v = 0.f;
            g_wpm[e] = v;
        } else {
            int e2 = e - n_pm;
            int k = e2 >> 7, co = e2 & 127;
            int ci = k / 9, n = k - ci * 9;
            g_wc[e2] = wc[(co * C + ci) * 9 + n];
        }
    }
}

// ---------------------------------------------------------------------------
// Kernel 2: pad + transpose NCHW -> padded NHWC
__global__ void pad_transpose_kernel(const float* __restrict__ x) {
    __shared__ float tile[32][33];
    int w0 = blockIdx.x * 32;
    int c0 = blockIdx.y * 32;
    int bh = blockIdx.z;
    int b = bh >> 7, h = bh & 127;
    int tx = threadIdx.x, ty = threadIdx.y;
#pragma unroll
    for (int r = 0; r < 4; ++r) {
        int ci = c0 + ty + r * 8;
        tile[ty + r * 8][tx] = x[(((size_t)b * C + ci) * H + h) * W + w0 + tx];
    }
    __syncthreads();
#pragma unroll
    for (int r = 0; r < 4; ++r) {
        int w = w0 + ty + r * 8;
        g_xp[(((size_t)b * HP + h + 1) * WP + (w + 1)) * C + c0 + tx] = tile[tx][ty + r * 8];
    }
}

// ---------------------------------------------------------------------------
// Kernel 3a: offset/mask conv, split-K x4, 2 output rows per block.
// Vectorized weight LDS (float4, ch padded to 28); weights amortized over 2 rows.
__global__ __launch_bounds__(128) void off_part_kernel() {
    __shared__ float ws8[8 * 9 * 28];       // 2016 floats
    __shared__ float xs[4 * 8 * 131];       // 4 rows x 8 ci x 131 w (transposed)
    int s = blockIdx.x;                      // slab 0..3
    int pr = blockIdx.y;                     // row pair 0..63
    int b = blockIdx.z;
    int h0 = pr * 2;
    int tx = threadIdx.x;

    float acc0[28], acc1[28];
#pragma unroll
    for (int ch = 0; ch < 28; ++ch) { acc0[ch] = 0.f; acc1[ch] = 0.f; }

    const float4* xp4 = reinterpret_cast<const float4*>(g_xp);

    for (int c8 = 0; c8 < 4; ++c8) {
        __syncthreads();
        // stage 8-ci weight slice (2016 floats)
        {
            const float4* wsrc = reinterpret_cast<const float4*>(g_wpm + (s * 32 + c8 * 8) * 9 * 28);
            float4* wdst = reinterpret_cast<float4*>(ws8);
            for (int i = tx; i < 504; i += 128) wdst[i] = wsrc[i];
        }
        // stage x: 4 rows (padded h0..h0+3) x 130 w x 8 ci, transposed to [row][ci][w]
#pragma unroll
        for (int row = 0; row < 4; ++row) {
            for (int i = tx; i < 260; i += 128) {
                int wq = i >> 1, cq = i & 1;
                float4 v = xp4[(((size_t)b * HP + h0 + row) * WP + wq) * 32 + s * 8 + c8 * 2 + cq];
                float* xd = xs + (row * 8 + cq * 4) * 131 + wq;
                xd[0]   = v.x;
                xd[131] = v.y;
                xd[262] = v.z;
                xd[393] = v.w;
            }
        }
        __syncthreads();
#pragma unroll
        for (int dh = 0; dh < 3; ++dh) {
#pragma unroll
            for (int j = 0; j < 8; ++j) {
                const float* xr0 = xs + ((dh + 0) * 8 + j) * 131 + tx;
                const float* xr1 = xs + ((dh + 1) * 8 + j) * 131 + tx;
                float a0 = xr0[0], a1 = xr0[1], a2 = xr0[2];
                float b0 = xr1[0], b1 = xr1[1], b2 = xr1[2];
#pragma unroll
                for (int dw = 0; dw < 3; ++dw) {
                    int tap = dh * 3 + dw;
                    float xv0 = (dw == 0) ? a0 : (dw == 1) ? a1 : a2;
                    float xv1 = (dw == 0) ? b0 : (dw == 1) ? b1 : b2;
                    const float4* wr = reinterpret_cast<const float4*>(ws8 + (j * 9 + tap) * 28);
#pragma unroll
                    for (int q = 0; q < 7; ++q) {
                        float4 wv = wr[q];
                        acc0[q * 4 + 0] = fmaf(xv0, wv.x, acc0[q * 4 + 0]);
                        acc0[q * 4 + 1] = fmaf(xv0, wv.y, acc0[q * 4 + 1]);
                        acc0[q * 4 + 2] = fmaf(xv0, wv.z, acc0[q * 4 + 2]);
                        acc0[q * 4 + 3] = fmaf(xv0, wv.w, acc0[q * 4 + 3]);
                        acc1[q * 4 + 0] = fmaf(xv1, wv.x, acc1[q * 4 + 0]);
                        acc1[q * 4 + 1] = fmaf(xv1, wv.y, acc1[q * 4 + 1]);
                        acc1[q * 4 + 2] = fmaf(xv1, wv.z, acc1[q * 4 + 2]);
                        acc1[q * 4 + 3] = fmaf(xv1, wv.w, acc1[q * 4 + 3]);
                    }
                }
            }
        }
    }
    int pix0 = (b * H + h0) * W + tx;
#pragma unroll
    for (int ch = 0; ch < 27; ++ch) {
        g_part[(s * 27 + ch) * (B * H * W) + pix0]     = acc0[ch];
        g_part[(s * 27 + ch) * (B * H * W) + pix0 + W] = acc1[ch];
    }
}

// ---------------------------------------------------------------------------
// Kernel 3b: combine partials + bias, sigmoid, bilinear gate/index precompute.
__global__ __launch_bounds__(128) void off_comb_kernel(const float* __restrict__ bp,
                                                       const float* __restrict__ bm) {
    int bh = blockIdx.x;
    int b = bh >> 7, h = bh & 127;
    int w = threadIdx.x;
    int pix = bh * 128 + w;

    float acc[27];
#pragma unroll
    for (int ch = 0; ch < 18; ++ch) acc[ch] = bp[ch];
#pragma unroll
    for (int ch = 0; ch < 9; ++ch) acc[18 + ch] = bm[ch];
#pragma unroll
    for (int s = 0; s < 4; ++s)
#pragma unroll
        for (int ch = 0; ch < 27; ++ch)
            acc[ch] += g_part[(s * 27 + ch) * (B * H * W) + pix];

    size_t base = (size_t)pix * 36;
#pragma unroll
    for (int n = 0; n < NPT; ++n) {
        float m = 1.f / (1.f + expf(-acc[18 + n]));
        float px = acc[n]     + (float)(h + 1) + (float)(n / 3 - 1);
        float py = acc[9 + n] + (float)(w + 1) + (float)(n % 3 - 1);
        float fx = floorf(px), fy = floorf(py);
        float qltx = fminf(fmaxf(fx,       0.f), 129.f);
        float qlty = fminf(fmaxf(fy,       0.f), 129.f);
        float qrbx = fminf(fmaxf(fx + 1.f, 0.f), 129.f);
        float qrby = fminf(fmaxf(fy + 1.f, 0.f), 129.f);
        float pxc = fminf(fmaxf(px, 0.f), 129.f);
        float pyc = fminf(fmaxf(py, 0.f), 129.f);
        float ax = 1.f + (qltx - pxc);
        float bx = 1.f - (qrbx - pxc);
        float ay = 1.f + (qlty - pyc);
        float by = 1.f - (qrby - pyc);
        int ilt_x = (int)qltx, ilt_y = (int)qlty;
        int irb_x = (int)qrbx, irb_y = (int)qrby;
        g_gates[base + n * 4 + 0] = ax * ay * m;
        g_gates[base + n * 4 + 1] = bx * by * m;
        g_gates[base + n * 4 + 2] = ax * by * m;
        g_gates[base + n * 4 + 3] = bx * ay * m;
        g_offs [base + n * 4 + 0] = ilt_x * WP + ilt_y;
        g_offs [base + n * 4 + 1] = irb_x * WP + irb_y;
        g_offs [base + n * 4 + 2] = ilt_x * WP + irb_y;
        g_offs [base + n * 4 + 3] = irb_x * WP + ilt_y;
    }
}

// ---------------------------------------------------------------------------
// Kernel 4: fused bilinear gather + GEMM.
// Block: 64 pixels x 128 co, 256 threads, 2 pixels x 16 co per thread.
#define TPX 64
#define KC2 72
#define USTR 66
__global__ __launch_bounds__(256, 2) void main_kernel(float* __restrict__ out) {
    extern __shared__ float smem[];
    float* w_s  = smem;                         // 72*128 = 9216 floats
    float* u_s  = smem + 9216;                  // 72*66  = 4752 floats
    float* gt_s = u_s + KC2 * USTR;             // 64*36  = 2304 floats
    int*   of_s = reinterpret_cast<int*>(gt_s + TPX * 36);  // 2304 ints

    int tid = threadIdx.x;
    int b = blockIdx.z, h = blockIdx.y, w0 = blockIdx.x * TPX;
    int pix0 = h * W + w0;

    {
        const float* gsrc = g_gates + (size_t)(b * (H * W) + pix0) * 36;
        const int*   osrc = g_offs  + (size_t)(b * (H * W) + pix0) * 36;
        for (int i = tid; i < TPX * 36; i += 256) {
            gt_s[i] = gsrc[i];
            of_s[i] = osrc[i];
        }
    }

    const float4* xb4 = reinterpret_cast<const float4*>(g_xp) + (size_t)b * HP * WP * 32;

    int p = tid & 31;          // pixel pair (pixels 2p, 2p+1)
    int g = tid >> 5;          // co group
    int co0 = g * 16;

    float acc[32];
#pragma unroll
    for (int j = 0; j < 32; ++j) acc[j] = 0.f;

    for (int chunk = 0; chunk < 16; ++chunk) {
        __syncthreads();
        // weights: 72 x 128 = 2304 float4
        {
            const float4* wsrc = reinterpret_cast<const float4*>(g_wc) + chunk * 2304;
            float4* wdst = reinterpret_cast<float4*>(w_s);
#pragma unroll
            for (int i = 0; i < 9; ++i)
                wdst[tid + i * 256] = wsrc[tid + i * 256];
        }
        // gather u tile: 64 pixels x 18 (q,n) entries, layout u_s[k][pix]
        for (int i = tid; i < TPX * 18; i += 256) {
            int pix = i / 18;
            int rr = i - pix * 18;
            int q = rr / 9;
            int n = rr - q * 9;
            int gidx = pix * 36 + n * 4;
            float g0 = gt_s[gidx + 0], g1 = gt_s[gidx + 1];
            float g2 = gt_s[gidx + 2], g3 = gt_s[gidx + 3];
            int o0 = of_s[gidx + 0], o1 = of_s[gidx + 1];
            int o2 = of_s[gidx + 2], o3 = of_s[gidx + 3];
            int cb = chunk * 2 + q;
            float4 v0 = xb4[o0 * 32 + cb];
            float4 v1 = xb4[o1 * 32 + cb];
            float4 v2 = xb4[o2 * 32 + cb];
            float4 v3 = xb4[o3 * 32 + cb];
            float* ud = u_s + (q * 36 + n) * USTR + pix;
            ud[0 * 9 * USTR]  = fmaf(g3, v3.x, fmaf(g2, v2.x, fmaf(g1, v1.x, g0 * v0.x)));
            ud[1 * 9 * USTR]  = fmaf(g3, v3.y, fmaf(g2, v2.y, fmaf(g1, v1.y, g0 * v0.y)));
            ud[2 * 9 * USTR]  = fmaf(g3, v3.z, fmaf(g2, v2.z, fmaf(g1, v1.z, g0 * v0.z)));
            ud[3 * 9 * USTR]  = fmaf(g3, v3.w, fmaf(g2, v2.w, fmaf(g1, v1.w, g0 * v0.w)));
        }
        __syncthreads();

        // GEMM: 2 pixels x 16 co per thread
        const float* up  = u_s + 2 * p;
        const float* wp0 = w_s + co0;
#pragma unroll 2
        for (int k = 0; k < KC2; ++k) {
            float2 uv = *reinterpret_cast<const float2*>(up + k * USTR);
            const float4* wr = reinterpret_cast<const float4*>(wp0 + k * 128);
            float4 wa = wr[0], wb = wr[1], wc2 = wr[2], wd = wr[3];
            acc[0]  = fmaf(uv.x, wa.x,  acc[0]);   acc[16] = fmaf(uv.y, wa.x,  acc[16]);
            acc[1]  = fmaf(uv.x, wa.y,  acc[1]);   acc[17] = fmaf(uv.y, wa.y,  acc[17]);
            acc[2]  = fmaf(uv.x, wa.z,  acc[2]);   acc[18] = fmaf(uv.y, wa.z,  acc[18]);
            acc[3]  = fmaf(uv.x, wa.w,  acc[3]);   acc[19] = fmaf(uv.y, wa.w,  acc[19]);
            acc[4]  = fmaf(uv.x, wb.x,  acc[4]);   acc[20] = fmaf(uv.y, wb.x,  acc[20]);
            acc[5]  = fmaf(uv.x, wb.y,  acc[5]);   acc[21] = fmaf(uv.y, wb.y,  acc[21]);
            acc[6]  = fmaf(uv.x, wb.z,  acc[6]);   acc[22] = fmaf(uv.y, wb.z,  acc[22]);
            acc[7]  = fmaf(uv.x, wb.w,  acc[7]);   acc[23] = fmaf(uv.y, wb.w,  acc[23]);
            acc[8]  = fmaf(uv.x, wc2.x, acc[8]);   acc[24] = fmaf(uv.y, wc2.x, acc[24]);
            acc[9]  = fmaf(uv.x, wc2.y, acc[9]);   acc[25] = fmaf(uv.y, wc2.y, acc[25]);
            acc[10] = fmaf(uv.x, wc2.z, acc[10]);  acc[26] = fmaf(uv.y, wc2.z, acc[26]);
            acc[11] = fmaf(uv.x, wc2.w, acc[11]);  acc[27] = fmaf(uv.y, wc2.w, acc[27]);
            acc[12] = fmaf(uv.x, wd.x,  acc[12]);  acc[28] = fmaf(uv.y, wd.x,  acc[28]);
            acc[13] = fmaf(uv.x, wd.y,  acc[13]);  acc[29] = fmaf(uv.y, wd.y,  acc[29]);
            acc[14] = fmaf(uv.x, wd.z,  acc[14]);  acc[30] = fmaf(uv.y, wd.z,  acc[30]);
            acc[15] = fmaf(uv.x, wd.w,  acc[15]);  acc[31] = fmaf(uv.y, wd.w,  acc[31]);
        }
    }

#pragma unroll
    for (int j = 0; j < 16; ++j) {
        int co = co0 + j;
        float2 v = make_float2(acc[j], acc[16 + j]);
        *reinterpret_cast<float2*>(out + (((size_t)b * CO + co) * H + h) * W + w0 + 2 * p) = v;
    }
}

// ---------------------------------------------------------------------------
extern "C" void kernel_launch(void* const* d_in, const int* in_sizes, int n_in,
                              void* d_out, int out_size) {
    const float* x      = (const float*)d_in[0];
    const float* w_p    = (const float*)d_in[1];
    const float* b_p    = (const float*)d_in[2];
    const float* w_m    = (const float*)d_in[3];
    const float* b_m    = (const float*)d_in[4];
    const float* w_conv = (const float*)d_in[5];
    float* out = (float*)d_out;

    static const int kMainSmem = (KC2 * 128 + KC2 * USTR + TPX * 36 * 2) * 4;  // 74304 B
    cudaFuncSetAttribute(main_kernel, cudaFuncAttributeMaxDynamicSharedMemorySize, kMainSmem);

    zero_xp_kernel<<<1024, 256>>>();
    prep_weights_kernel<<<702, 256>>>(w_p, w_m, w_conv);
    pad_transpose_kernel<<<dim3(W / 32, C / 32, B * H), dim3(32, 8)>>>(x);
    off_part_kernel<<<dim3(4, 64, B), 128>>>();
    off_comb_kernel<<<B * H, 128>>>(b_p, b_m);
    main_kernel<<<dim3(W / TPX, H, B), 256, kMainSmem>>>(out);
}

// round 5
// speedup vs baseline: 2.3763x; 1.9084x over previous
#include <cuda_runtime.h>
#include <cuda_bf16.h>
#include <math.h>
#include <stdint.h>

// Problem constants
#define B 2
#define C 128
#define H 128
#define W 128
#define HP 130
#define WP 130
#define NPT 9
#define CO 128
#define BHW (B * H * W)

// Scratch (device globals; allocation-free)
__device__ __align__(16) float g_xp[B * HP * WP * C];           // padded NHWC x (~17.3 MB)
__device__ __align__(16) float4 g_gates2[NPT * BHW];            // gates [n][pix] (lt,rb,lb,rt)
__device__ __align__(16) int4   g_offs2 [NPT * BHW];            // corner offsets [n][pix]
__device__ __align__(16) float g_wpm[C * NPT * 28];             // offset/mask weights (ch padded 28)
__device__ __align__(16) float g_part[4 * 27 * BHW];            // split-K partials
// bf16 hi/lo weight tiles: 18 tiles (tap n x ci-half) of [co 128][k 64], linear
__device__ __align__(16) unsigned short g_wA_hi[18 * 8192];
__device__ __align__(16) unsigned short g_wA_lo[18 * 8192];

// ---------------------------------------------------------------------------
// PTX helpers (all sm_80-era: no arch-"a" gated instructions)
__device__ __forceinline__ uint32_t smem_u32(const void* p) {
    uint32_t a;
    asm("{ .reg .u64 t; cvta.to.shared.u64 t, %1; cvt.u32.u64 %0, t; }" : "=r"(a) : "l"(p));
    return a;
}
__device__ __forceinline__ void ldmx4(uint32_t* r, uint32_t a) {
    asm volatile("ldmatrix.sync.aligned.m8n8.x4.shared.b16 {%0,%1,%2,%3}, [%4];"
                 : "=r"(r[0]), "=r"(r[1]), "=r"(r[2]), "=r"(r[3]) : "r"(a));
}
__device__ __forceinline__ void ldmx2(uint32_t& r0, uint32_t& r1, uint32_t a) {
    asm volatile("ldmatrix.sync.aligned.m8n8.x2.shared.b16 {%0,%1}, [%2];"
                 : "=r"(r0), "=r"(r1) : "r"(a));
}
__device__ __forceinline__ void mma_bf16(float* c, const uint32_t* a, uint32_t b0, uint32_t b1) {
    asm volatile(
        "mma.sync.aligned.m16n8k16.row.col.f32.bf16.bf16.f32 "
        "{%0,%1,%2,%3}, {%4,%5,%6,%7}, {%8,%9}, {%0,%1,%2,%3};"
        : "+f"(c[0]), "+f"(c[1]), "+f"(c[2]), "+f"(c[3])
        : "r"(a[0]), "r"(a[1]), "r"(a[2]), "r"(a[3]), "r"(b0), "r"(b1));
}

// ---------------------------------------------------------------------------
// Kernel 0: zero padded buffer
__global__ void zero_xp_kernel() {
    const int total = B * HP * WP * C / 4;
    float4* p = reinterpret_cast<float4*>(g_xp);
    float4 z = make_float4(0.f, 0.f, 0.f, 0.f);
    for (int i = blockIdx.x * blockDim.x + threadIdx.x; i < total; i += gridDim.x * blockDim.x)
        p[i] = z;
}

// ---------------------------------------------------------------------------
// Kernel 1: weight re-layouts (offset/mask padded; main conv -> bf16 hi/lo tiles)
__global__ void prep_weights_kernel(const float* __restrict__ wp,
                                    const float* __restrict__ wm,
                                    const float* __restrict__ wc) {
    const int n_pm = C * NPT * 28;           // 32256
    const int n_wa = 18 * 128 * 64;          // 147456
    for (int e = blockIdx.x * blockDim.x + threadIdx.x; e < n_pm + n_wa;
         e += gridDim.x * blockDim.x) {
        if (e < n_pm) {
            int k = e / 28, ch = e - k * 28;
            int ci = k / 9, tap = k - ci * 9;
            float v;
            if (ch < 18)      v = wp[(ch * C + ci) * 9 + tap];
            else if (ch < 27) v = wm[((ch - 18) * C + ci) * 9 + tap];
            else              v = 0.f;
            g_wpm[e] = v;
        } else {
            int t = e - n_pm;
            int tile = t >> 13;          // 0..17
            int r = t & 8191;
            int co = r >> 6;
            int c = r & 63;
            int n = tile >> 1, half = tile & 1;
            int ci = half * 64 + c;
            float v = wc[(co * C + ci) * 9 + n];
            __nv_bfloat16 hi = __float2bfloat16_rn(v);
            __nv_bfloat16 lo = __float2bfloat16_rn(v - __bfloat162float(hi));
            g_wA_hi[t] = __bfloat16_as_ushort(hi);
            g_wA_lo[t] = __bfloat16_as_ushort(lo);
        }
    }
}

// ---------------------------------------------------------------------------
// Kernel 2: pad + transpose NCHW -> padded NHWC
__global__ void pad_transpose_kernel(const float* __restrict__ x) {
    __shared__ float tile[32][33];
    int w0 = blockIdx.x * 32;
    int c0 = blockIdx.y * 32;
    int bh = blockIdx.z;
    int b = bh >> 7, h = bh & 127;
    int tx = threadIdx.x, ty = threadIdx.y;
#pragma unroll
    for (int r = 0; r < 4; ++r) {
        int ci = c0 + ty + r * 8;
        tile[ty + r * 8][tx] = x[(((size_t)b * C + ci) * H + h) * W + w0 + tx];
    }
    __syncthreads();
#pragma unroll
    for (int r = 0; r < 4; ++r) {
        int w = w0 + ty + r * 8;
        g_xp[(((size_t)b * HP + h + 1) * WP + (w + 1)) * C + c0 + tx] = tile[tx][ty + r * 8];
    }
}

// ---------------------------------------------------------------------------
// Kernel 3a: offset/mask conv, split-K x4, 2 output rows per block.
__global__ __launch_bounds__(128) void off_part_kernel() {
    __shared__ float ws8[8 * 9 * 28];
    __shared__ float xs[4 * 8 * 131];
    int s = blockIdx.x;
    int pr = blockIdx.y;
    int b = blockIdx.z;
    int h0 = pr * 2;
    int tx = threadIdx.x;

    float acc0[28], acc1[28];
#pragma unroll
    for (int ch = 0; ch < 28; ++ch) { acc0[ch] = 0.f; acc1[ch] = 0.f; }

    const float4* xp4 = reinterpret_cast<const float4*>(g_xp);

    for (int c8 = 0; c8 < 4; ++c8) {
        __syncthreads();
        {
            const float4* wsrc = reinterpret_cast<const float4*>(g_wpm + (s * 32 + c8 * 8) * 9 * 28);
            float4* wdst = reinterpret_cast<float4*>(ws8);
            for (int i = tx; i < 504; i += 128) wdst[i] = wsrc[i];
        }
#pragma unroll
        for (int row = 0; row < 4; ++row) {
            for (int i = tx; i < 260; i += 128) {
                int wq = i >> 1, cq = i & 1;
                float4 v = xp4[(((size_t)b * HP + h0 + row) * WP + wq) * 32 + s * 8 + c8 * 2 + cq];
                float* xd = xs + (row * 8 + cq * 4) * 131 + wq;
                xd[0]   = v.x;
                xd[131] = v.y;
                xd[262] = v.z;
                xd[393] = v.w;
            }
        }
        __syncthreads();
#pragma unroll
        for (int dh = 0; dh < 3; ++dh) {
#pragma unroll
            for (int j = 0; j < 8; ++j) {
                const float* xr0 = xs + ((dh + 0) * 8 + j) * 131 + tx;
                const float* xr1 = xs + ((dh + 1) * 8 + j) * 131 + tx;
                float a0 = xr0[0], a1 = xr0[1], a2 = xr0[2];
                float b0 = xr1[0], b1 = xr1[1], b2 = xr1[2];
#pragma unroll
                for (int dw = 0; dw < 3; ++dw) {
                    int tap = dh * 3 + dw;
                    float xv0 = (dw == 0) ? a0 : (dw == 1) ? a1 : a2;
                    float xv1 = (dw == 0) ? b0 : (dw == 1) ? b1 : b2;
                    const float4* wr = reinterpret_cast<const float4*>(ws8 + (j * 9 + tap) * 28);
#pragma unroll
                    for (int q = 0; q < 7; ++q) {
                        float4 wv = wr[q];
                        acc0[q * 4 + 0] = fmaf(xv0, wv.x, acc0[q * 4 + 0]);
                        acc0[q * 4 + 1] = fmaf(xv0, wv.y, acc0[q * 4 + 1]);
                        acc0[q * 4 + 2] = fmaf(xv0, wv.z, acc0[q * 4 + 2]);
                        acc0[q * 4 + 3] = fmaf(xv0, wv.w, acc0[q * 4 + 3]);
                        acc1[q * 4 + 0] = fmaf(xv1, wv.x, acc1[q * 4 + 0]);
                        acc1[q * 4 + 1] = fmaf(xv1, wv.y, acc1[q * 4 + 1]);
                        acc1[q * 4 + 2] = fmaf(xv1, wv.z, acc1[q * 4 + 2]);
                        acc1[q * 4 + 3] = fmaf(xv1, wv.w, acc1[q * 4 + 3]);
                    }
                }
            }
        }
    }
    int pix0 = (b * H + h0) * W + tx;
#pragma unroll
    for (int ch = 0; ch < 27; ++ch) {
        g_part[(s * 27 + ch) * BHW + pix0]     = acc0[ch];
        g_part[(s * 27 + ch) * BHW + pix0 + W] = acc1[ch];
    }
}

// ---------------------------------------------------------------------------
// Kernel 3b: combine partials + bias, sigmoid, gate/index precompute (tap-major)
__global__ __launch_bounds__(128) void off_comb_kernel(const float* __restrict__ bp,
                                                       const float* __restrict__ bm) {
    int bh = blockIdx.x;
    int b = bh >> 7, h = bh & 127;
    int w = threadIdx.x;
    int pix = bh * 128 + w;

    float acc[27];
#pragma unroll
    for (int ch = 0; ch < 18; ++ch) acc[ch] = bp[ch];
#pragma unroll
    for (int ch = 0; ch < 9; ++ch) acc[18 + ch] = bm[ch];
#pragma unroll
    for (int s = 0; s < 4; ++s)
#pragma unroll
        for (int ch = 0; ch < 27; ++ch)
            acc[ch] += g_part[(s * 27 + ch) * BHW + pix];

#pragma unroll
    for (int n = 0; n < NPT; ++n) {
        float m = 1.f / (1.f + expf(-acc[18 + n]));
        float px = acc[n]     + (float)(h + 1) + (float)(n / 3 - 1);
        float py = acc[9 + n] + (float)(w + 1) + (float)(n % 3 - 1);
        float fx = floorf(px), fy = floorf(py);
        float qltx = fminf(fmaxf(fx,       0.f), 129.f);
        float qlty = fminf(fmaxf(fy,       0.f), 129.f);
        float qrbx = fminf(fmaxf(fx + 1.f, 0.f), 129.f);
        float qrby = fminf(fmaxf(fy + 1.f, 0.f), 129.f);
        float pxc = fminf(fmaxf(px, 0.f), 129.f);
        float pyc = fminf(fmaxf(py, 0.f), 129.f);
        float ax = 1.f + (qltx - pxc);
        float bx = 1.f - (qrbx - pxc);
        float ay = 1.f + (qlty - pyc);
        float by = 1.f - (qrby - pyc);
        int ilt_x = (int)qltx, ilt_y = (int)qlty;
        int irb_x = (int)qrbx, irb_y = (int)qrby;
        g_gates2[n * BHW + pix] = make_float4(ax * ay * m, bx * by * m, ax * by * m, bx * ay * m);
        g_offs2 [n * BHW + pix] = make_int4(ilt_x * WP + ilt_y, irb_x * WP + irb_y,
                                            ilt_x * WP + irb_y, irb_x * WP + ilt_y);
    }
}

// ---------------------------------------------------------------------------
// Kernel 4: fused gather + bf16-split GEMM on warp-level mma (HMMA).
// CTA = 128 co x 64 pixels. 256 thr, 8 warps (2 co-halves x 4 pixel-quarters).
// K = 1152 as 18 chunks of 64. D = W_hi*U_hi + W_lo*U_hi + W_hi*U_lo (fp32 acc).
// smem rows padded to 144B -> conflict-free ldmatrix.
#define SM_WHI 0
#define SM_WLO 18432
#define SM_UHI 36864
#define SM_ULO 46080
#define SM_TOTAL 55296
__global__ __launch_bounds__(256, 2) void mma_main_kernel(float* __restrict__ out) {
    extern __shared__ __align__(128) char smem[];
    uint32_t sb = smem_u32(smem);
    int tid = threadIdx.x;
    int wid = tid >> 5, lane = tid & 31;

    int idx = blockIdx.x;
    int b = idx >> 8;
    int h = (idx >> 1) & 127;
    int w0 = (idx & 1) * 64;

    // gather mapping: thread -> (pixel, ci quarter)
    int pixl = tid >> 2;             // 0..63
    int qt = tid & 3;                // 4 quads of 4 ci each
    int gpix = (b * H + h) * W + w0 + pixl;
    const float4* xb4 = reinterpret_cast<const float4*>(g_xp) + (size_t)b * HP * WP * 32;

    // warp tile: M=64 co, N=16 pixels
    int wm = (wid & 1) * 64;
    int wn = (wid >> 1) * 16;

    // ldmatrix per-lane address components
    int asel = lane >> 3;                            // 0..3
    int aRow = ((asel & 1) << 3) + (lane & 7);       // row within 16
    int aK = (asel >> 1) << 3;                       // k offset 0/8
    uint32_t aBase = (uint32_t)((wm + aRow) * 144 + aK * 2);
    uint32_t bBase = (uint32_t)((wn + (lane & 7)) * 144 + (((lane >> 3) & 1) << 3) * 2);

    float acc[4][2][4];
#pragma unroll
    for (int mt = 0; mt < 4; ++mt)
#pragma unroll
        for (int nt = 0; nt < 2; ++nt)
#pragma unroll
            for (int j = 0; j < 4; ++j) acc[mt][nt][j] = 0.f;

    for (int chunk = 0; chunk < 18; ++chunk) {
        int n = chunk >> 1, half = chunk & 1;
        __syncthreads();

        // stage weight tiles (linear gmem -> 144B-padded smem rows)
        {
            const float4* ah = reinterpret_cast<const float4*>(g_wA_hi) + chunk * 1024;
            const float4* al = reinterpret_cast<const float4*>(g_wA_lo) + chunk * 1024;
#pragma unroll
            for (int i = 0; i < 4; ++i) {
                int e = tid + i * 256;
                int off = (e >> 3) * 144 + (e & 7) * 16;
                *reinterpret_cast<float4*>(smem + SM_WHI + off) = ah[e];
                *reinterpret_cast<float4*>(smem + SM_WLO + off) = al[e];
            }
        }

        // gather + bf16 split into U tiles ([pix][k] = B^T layout)
        float4 g = g_gates2[n * BHW + gpix];
        int4  o = g_offs2 [n * BHW + gpix];
#pragma unroll
        for (int q = 0; q < 4; ++q) {
            int cb = half * 16 + qt * 4 + q;
            float4 v0 = xb4[(size_t)o.x * 32 + cb];
            float4 v1 = xb4[(size_t)o.y * 32 + cb];
            float4 v2 = xb4[(size_t)o.z * 32 + cb];
            float4 v3 = xb4[(size_t)o.w * 32 + cb];
            float4 v;
            v.x = fmaf(g.w, v3.x, fmaf(g.z, v2.x, fmaf(g.y, v1.x, g.x * v0.x)));
            v.y = fmaf(g.w, v3.y, fmaf(g.z, v2.y, fmaf(g.y, v1.y, g.x * v0.y)));
            v.z = fmaf(g.w, v3.z, fmaf(g.z, v2.z, fmaf(g.y, v1.z, g.x * v0.z)));
            v.w = fmaf(g.w, v3.w, fmaf(g.z, v2.w, fmaf(g.y, v1.w, g.x * v0.w)));

            __nv_bfloat16 hx = __float2bfloat16_rn(v.x);
            __nv_bfloat16 hy = __float2bfloat16_rn(v.y);
            __nv_bfloat16 hz = __float2bfloat16_rn(v.z);
            __nv_bfloat16 hw = __float2bfloat16_rn(v.w);
            __nv_bfloat16 lx = __float2bfloat16_rn(v.x - __bfloat162float(hx));
            __nv_bfloat16 ly = __float2bfloat16_rn(v.y - __bfloat162float(hy));
            __nv_bfloat16 lz = __float2bfloat16_rn(v.z - __bfloat162float(hz));
            __nv_bfloat16 lw = __float2bfloat16_rn(v.w - __bfloat162float(hw));

            uint32_t uoff = (uint32_t)(pixl * 144 + (qt * 4 + q) * 8);
            uint32_t hi0 = (uint32_t)__bfloat16_as_ushort(hx) | ((uint32_t)__bfloat16_as_ushort(hy) << 16);
            uint32_t hi1 = (uint32_t)__bfloat16_as_ushort(hz) | ((uint32_t)__bfloat16_as_ushort(hw) << 16);
            uint32_t lo0 = (uint32_t)__bfloat16_as_ushort(lx) | ((uint32_t)__bfloat16_as_ushort(ly) << 16);
            uint32_t lo1 = (uint32_t)__bfloat16_as_ushort(lz) | ((uint32_t)__bfloat16_as_ushort(lw) << 16);
            *reinterpret_cast<uint32_t*>(smem + SM_UHI + uoff)     = hi0;
            *reinterpret_cast<uint32_t*>(smem + SM_UHI + uoff + 4) = hi1;
            *reinterpret_cast<uint32_t*>(smem + SM_ULO + uoff)     = lo0;
            *reinterpret_cast<uint32_t*>(smem + SM_ULO + uoff + 4) = lo1;
        }
        __syncthreads();

        // HMMA: 4 k-steps of 16
#pragma unroll
        for (int ks = 0; ks < 4; ++ks) {
            uint32_t AH[4][4], AL[4][4];
#pragma unroll
            for (int mt = 0; mt < 4; ++mt) {
                uint32_t ao = aBase + (uint32_t)(mt * 16 * 144 + ks * 32);
                ldmx4(AH[mt], sb + SM_WHI + ao);
                ldmx4(AL[mt], sb + SM_WLO + ao);
            }
#pragma unroll
            for (int nt = 0; nt < 2; ++nt) {
                uint32_t bo = bBase + (uint32_t)(nt * 8 * 144 + ks * 32);
                uint32_t bh0, bh1, bl0, bl1;
                ldmx2(bh0, bh1, sb + SM_UHI + bo);
#pragma unroll
                for (int mt = 0; mt < 4; ++mt) mma_bf16(acc[mt][nt], AH[mt], bh0, bh1);
#pragma unroll
                for (int mt = 0; mt < 4; ++mt) mma_bf16(acc[mt][nt], AL[mt], bh0, bh1);
                ldmx2(bl0, bl1, sb + SM_ULO + bo);
#pragma unroll
                for (int mt = 0; mt < 4; ++mt) mma_bf16(acc[mt][nt], AH[mt], bl0, bl1);
            }
        }
    }

    // epilogue: D fragment lane mapping: rows co = g4 (+8), cols pix = t4*2,+1
    int g4 = lane >> 2, t4 = lane & 3;
#pragma unroll
    for (int mt = 0; mt < 4; ++mt) {
#pragma unroll
        for (int nt = 0; nt < 2; ++nt) {
            int co = wm + mt * 16 + g4;
            int px = w0 + wn + nt * 8 + t4 * 2;
            float* op = out + (((size_t)b * CO + co) * H + h) * W + px;
            *reinterpret_cast<float2*>(op) = make_float2(acc[mt][nt][0], acc[mt][nt][1]);
            float* op2 = out + (((size_t)b * CO + co + 8) * H + h) * W + px;
            *reinterpret_cast<float2*>(op2) = make_float2(acc[mt][nt][2], acc[mt][nt][3]);
        }
    }
}

// ---------------------------------------------------------------------------
extern "C" void kernel_launch(void* const* d_in, const int* in_sizes, int n_in,
                              void* d_out, int out_size) {
    const float* x      = (const float*)d_in[0];
    const float* w_p    = (const float*)d_in[1];
    const float* b_p    = (const float*)d_in[2];
    const float* w_m    = (const float*)d_in[3];
    const float* b_m    = (const float*)d_in[4];
    const float* w_conv = (const float*)d_in[5];
    float* out = (float*)d_out;

    cudaFuncSetAttribute(mma_main_kernel, cudaFuncAttributeMaxDynamicSharedMemorySize, SM_TOTAL);

    zero_xp_kernel<<<1024, 256>>>();
    prep_weights_kernel<<<702, 256>>>(w_p, w_m, w_conv);
    pad_transpose_kernel<<<dim3(W / 32, C / 32, B * H), dim3(32, 8)>>>(x);
    off_part_kernel<<<dim3(4, 64, B), 128>>>();
    off_comb_kernel<<<B * H, 128>>>(b_p, b_m);
    mma_main_kernel<<<512, 256, SM_TOTAL>>>(out);
}

// round 6
// speedup vs baseline: 2.4967x; 1.0507x over previous
#include <cuda_runtime.h>
#include <cuda_bf16.h>
#include <math.h>
#include <stdint.h>

// Problem constants
#define B 2
#define C 128
#define H 128
#define W 128
#define HP 130
#define WP 130
#define NPT 9
#define CO 128
#define BHW (B * H * W)

// Scratch (device globals; allocation-free)
__device__ __align__(16) float g_xp[B * HP * WP * C];           // padded NHWC x (~17.3 MB)
__device__ __align__(16) float4 g_gates2[NPT * BHW];            // gates [n][pix] (lt,rb,lb,rt)
__device__ __align__(16) int4   g_offs2 [NPT * BHW];            // corner offsets [n][pix]
__device__ __align__(16) float g_part[27 * BHW];                // offset conv outputs [ch][pix]
// bf16 hi/lo weight tiles, 18 tiles (tap n x ci-half):
//   main conv:   [co 128][k 64]
//   offset conv: [ch 32(27 pad)][k 64]
__device__ __align__(16) unsigned short g_wA_hi[18 * 8192];
__device__ __align__(16) unsigned short g_wA_lo[18 * 8192];
__device__ __align__(16) unsigned short g_wO_hi[18 * 2048];
__device__ __align__(16) unsigned short g_wO_lo[18 * 2048];

// ---------------------------------------------------------------------------
// PTX helpers (all sm_80-era: no arch-"a" gated instructions)
__device__ __forceinline__ uint32_t smem_u32(const void* p) {
    uint32_t a;
    asm("{ .reg .u64 t; cvta.to.shared.u64 t, %1; cvt.u32.u64 %0, t; }" : "=r"(a) : "l"(p));
    return a;
}
__device__ __forceinline__ void ldmx4(uint32_t* r, uint32_t a) {
    asm volatile("ldmatrix.sync.aligned.m8n8.x4.shared.b16 {%0,%1,%2,%3}, [%4];"
                 : "=r"(r[0]), "=r"(r[1]), "=r"(r[2]), "=r"(r[3]) : "r"(a));
}
__device__ __forceinline__ void ldmx2(uint32_t& r0, uint32_t& r1, uint32_t a) {
    asm volatile("ldmatrix.sync.aligned.m8n8.x2.shared.b16 {%0,%1}, [%2];"
                 : "=r"(r0), "=r"(r1) : "r"(a));
}
__device__ __forceinline__ void mma_bf16(float* c, const uint32_t* a, uint32_t b0, uint32_t b1) {
    asm volatile(
        "mma.sync.aligned.m16n8k16.row.col.f32.bf16.bf16.f32 "
        "{%0,%1,%2,%3}, {%4,%5,%6,%7}, {%8,%9}, {%0,%1,%2,%3};"
        : "+f"(c[0]), "+f"(c[1]), "+f"(c[2]), "+f"(c[3])
        : "r"(a[0]), "r"(a[1]), "r"(a[2]), "r"(a[3]), "r"(b0), "r"(b1));
}
__device__ __forceinline__ void bf16_split(float v, uint16_t& hi, uint16_t& lo) {
    __nv_bfloat16 h = __float2bfloat16_rn(v);
    __nv_bfloat16 l = __float2bfloat16_rn(v - __bfloat162float(h));
    hi = __bfloat16_as_ushort(h);
    lo = __bfloat16_as_ushort(l);
}

// ---------------------------------------------------------------------------
// Kernel 0: zero only the pad border of g_xp (interior fully overwritten)
__global__ void zero_border_kernel() {
    int i = blockIdx.x * blockDim.x + threadIdx.x;
    if (i >= B * 516 * 32) return;
    int q = i & 31;
    int p = i >> 5;
    int b = p / 516;
    int r = p - b * 516;
    int hh, ww;
    if (r < 130)      { hh = 0;        ww = r; }
    else if (r < 260) { hh = 129;      ww = r - 130; }
    else if (r < 388) { hh = r - 259;  ww = 0; }
    else              { hh = r - 387;  ww = 129; }
    reinterpret_cast<float4*>(g_xp)[((size_t)(b * HP + hh) * WP + ww) * 32 + q] =
        make_float4(0.f, 0.f, 0.f, 0.f);
}

// ---------------------------------------------------------------------------
// Kernel 1: weight re-layouts -> bf16 hi/lo tiles (main + offset conv)
__global__ void prep_weights_kernel(const float* __restrict__ wp,
                                    const float* __restrict__ wm,
                                    const float* __restrict__ wc) {
    const int n_off = 18 * 32 * 64;          // 36864
    const int n_wa  = 18 * 128 * 64;         // 147456
    for (int e = blockIdx.x * blockDim.x + threadIdx.x; e < n_off + n_wa;
         e += gridDim.x * blockDim.x) {
        if (e < n_off) {
            int tile = e >> 11;
            int r = e & 2047;
            int ch = r >> 6;
            int c = r & 63;
            int n = tile >> 1, half = tile & 1;
            int ci = half * 64 + c;
            float v = 0.f;
            if (ch < 18)      v = wp[(ch * C + ci) * 9 + n];
            else if (ch < 27) v = wm[((ch - 18) * C + ci) * 9 + n];
            uint16_t hi, lo;
            bf16_split(v, hi, lo);
            g_wO_hi[e] = hi;
            g_wO_lo[e] = lo;
        } else {
            int t = e - n_off;
            int tile = t >> 13;
            int r = t & 8191;
            int co = r >> 6;
            int c = r & 63;
            int n = tile >> 1, half = tile & 1;
            int ci = half * 64 + c;
            float v = wc[(co * C + ci) * 9 + n];
            uint16_t hi, lo;
            bf16_split(v, hi, lo);
            g_wA_hi[t] = hi;
            g_wA_lo[t] = lo;
        }
    }
}

// ---------------------------------------------------------------------------
// Kernel 2: pad + transpose NCHW -> padded NHWC
__global__ void pad_transpose_kernel(const float* __restrict__ x) {
    __shared__ float tile[32][33];
    int w0 = blockIdx.x * 32;
    int c0 = blockIdx.y * 32;
    int bh = blockIdx.z;
    int b = bh >> 7, h = bh & 127;
    int tx = threadIdx.x, ty = threadIdx.y;
#pragma unroll
    for (int r = 0; r < 4; ++r) {
        int ci = c0 + ty + r * 8;
        tile[ty + r * 8][tx] = x[(((size_t)b * C + ci) * H + h) * W + w0 + tx];
    }
    __syncthreads();
#pragma unroll
    for (int r = 0; r < 4; ++r) {
        int w = w0 + ty + r * 8;
        g_xp[(((size_t)b * HP + h + 1) * WP + (w + 1)) * C + c0 + tx] = tile[tx][ty + r * 8];
    }
}

// ---------------------------------------------------------------------------
// Kernel 3a: offset/mask conv via HMMA (bf16 hi/lo split, no gather — im2col rows).
// CTA = 32 ch x 64 pixels. 256 thr, 8 warps (2 ch-halves x 4 pixel-quarters).
#define SC_WHI 0
#define SC_WLO 4608
#define SC_UHI 9216
#define SC_ULO 18432
#define SC_TOTAL 27648
__global__ __launch_bounds__(256) void conv_mma_kernel() {
    extern __shared__ __align__(128) char smem[];
    uint32_t sb = smem_u32(smem);
    int tid = threadIdx.x;
    int wid = tid >> 5, lane = tid & 31;

    int idx = blockIdx.x;
    int b = idx >> 8;
    int h = (idx >> 1) & 127;
    int w0 = (idx & 1) * 64;

    int pixl = tid >> 2;
    int qt = tid & 3;
    const float4* xb4 = reinterpret_cast<const float4*>(g_xp) + (size_t)b * HP * WP * 32;

    int wm = (wid & 1) * 16;
    int wn = (wid >> 1) * 16;

    int asel = lane >> 3;
    int aRow = ((asel & 1) << 3) + (lane & 7);
    int aK = (asel >> 1) << 3;
    uint32_t aBase = (uint32_t)((wm + aRow) * 144 + aK * 2);
    uint32_t bBase = (uint32_t)((wn + (lane & 7)) * 144 + (((lane >> 3) & 1) << 3) * 2);

    float acc[2][4];
#pragma unroll
    for (int nt = 0; nt < 2; ++nt)
#pragma unroll
        for (int j = 0; j < 4; ++j) acc[nt][j] = 0.f;

    for (int chunk = 0; chunk < 18; ++chunk) {
        int n = chunk >> 1, half = chunk & 1;
        int dh = n / 3, dw = n - dh * 3;
        __syncthreads();

        // stage W tiles (32 rows x 128B, padded to 144B rows)
        {
            int off = (tid >> 3) * 144 + (tid & 7) * 16;
            *reinterpret_cast<float4*>(smem + SC_WHI + off) =
                reinterpret_cast<const float4*>(g_wO_hi)[chunk * 256 + tid];
            *reinterpret_cast<float4*>(smem + SC_WLO + off) =
                reinterpret_cast<const float4*>(g_wO_lo)[chunk * 256 + tid];
        }

        // build U tile: u[pix][c] = xp[h+dh][w0+pix+dw][half*64+c] (contiguous, no gather)
        {
            size_t row = ((size_t)(b * 0 + h + dh) * WP + (w0 + pixl + dw));  // b folded into xb4
            const float4* src = xb4 + row * 32 + half * 16 + qt * 4;
#pragma unroll
            for (int q = 0; q < 4; ++q) {
                float4 v = src[q];
                uint16_t hx, lx, hy, ly, hz, lz, hw_, lw_;
                bf16_split(v.x, hx, lx);
                bf16_split(v.y, hy, ly);
                bf16_split(v.z, hz, lz);
                bf16_split(v.w, hw_, lw_);
                uint32_t uoff = (uint32_t)(pixl * 144 + (qt * 4 + q) * 8);
                *reinterpret_cast<uint32_t*>(smem + SC_UHI + uoff)     = (uint32_t)hx | ((uint32_t)hy << 16);
                *reinterpret_cast<uint32_t*>(smem + SC_UHI + uoff + 4) = (uint32_t)hz | ((uint32_t)hw_ << 16);
                *reinterpret_cast<uint32_t*>(smem + SC_ULO + uoff)     = (uint32_t)lx | ((uint32_t)ly << 16);
                *reinterpret_cast<uint32_t*>(smem + SC_ULO + uoff + 4) = (uint32_t)lz | ((uint32_t)lw_ << 16);
            }
        }
        __syncthreads();

#pragma unroll
        for (int ks = 0; ks < 4; ++ks) {
            uint32_t AH[4], AL[4];
            uint32_t ao = aBase + (uint32_t)(ks * 32);
            ldmx4(AH, sb + SC_WHI + ao);
            ldmx4(AL, sb + SC_WLO + ao);
#pragma unroll
            for (int nt = 0; nt < 2; ++nt) {
                uint32_t bo = bBase + (uint32_t)(nt * 8 * 144 + ks * 32);
                uint32_t bh0, bh1, bl0, bl1;
                ldmx2(bh0, bh1, sb + SC_UHI + bo);
                mma_bf16(acc[nt], AH, bh0, bh1);
                mma_bf16(acc[nt], AL, bh0, bh1);
                ldmx2(bl0, bl1, sb + SC_ULO + bo);
                mma_bf16(acc[nt], AH, bl0, bl1);
            }
        }
    }

    int g4 = lane >> 2, t4 = lane & 3;
    int pixbase = (b * H + h) * W + w0;
#pragma unroll
    for (int nt = 0; nt < 2; ++nt) {
        int px = wn + nt * 8 + t4 * 2;
        int ch = wm + g4;
        if (ch < 27)
            *reinterpret_cast<float2*>(&g_part[(size_t)ch * BHW + pixbase + px]) =
                make_float2(acc[nt][0], acc[nt][1]);
        if (ch + 8 < 27)
            *reinterpret_cast<float2*>(&g_part[(size_t)(ch + 8) * BHW + pixbase + px]) =
                make_float2(acc[nt][2], acc[nt][3]);
    }
}

// ---------------------------------------------------------------------------
// Kernel 3b: bias + sigmoid + bilinear gate/index precompute (tap-major layout)
__global__ __launch_bounds__(128) void off_comb_kernel(const float* __restrict__ bp,
                                                       const float* __restrict__ bm) {
    int bh = blockIdx.x;
    int b = bh >> 7, h = bh & 127;
    int w = threadIdx.x;
    int pix = bh * 128 + w;

    float acc[27];
#pragma unroll
    for (int ch = 0; ch < 18; ++ch) acc[ch] = bp[ch] + g_part[(size_t)ch * BHW + pix];
#pragma unroll
    for (int ch = 18; ch < 27; ++ch) acc[ch] = bm[ch - 18] + g_part[(size_t)ch * BHW + pix];

#pragma unroll
    for (int n = 0; n < NPT; ++n) {
        float m = 1.f / (1.f + expf(-acc[18 + n]));
        float px = acc[n]     + (float)(h + 1) + (float)(n / 3 - 1);
        float py = acc[9 + n] + (float)(w + 1) + (float)(n % 3 - 1);
        float fx = floorf(px), fy = floorf(py);
        float qltx = fminf(fmaxf(fx,       0.f), 129.f);
        float qlty = fminf(fmaxf(fy,       0.f), 129.f);
        float qrbx = fminf(fmaxf(fx + 1.f, 0.f), 129.f);
        float qrby = fminf(fmaxf(fy + 1.f, 0.f), 129.f);
        float pxc = fminf(fmaxf(px, 0.f), 129.f);
        float pyc = fminf(fmaxf(py, 0.f), 129.f);
        float ax = 1.f + (qltx - pxc);
        float bx = 1.f - (qrbx - pxc);
        float ay = 1.f + (qlty - pyc);
        float by = 1.f - (qrby - pyc);
        int ilt_x = (int)qltx, ilt_y = (int)qlty;
        int irb_x = (int)qrbx, irb_y = (int)qrby;
        g_gates2[n * BHW + pix] = make_float4(ax * ay * m, bx * by * m, ax * by * m, bx * ay * m);
        g_offs2 [n * BHW + pix] = make_int4(ilt_x * WP + ilt_y, irb_x * WP + irb_y,
                                            ilt_x * WP + irb_y, irb_x * WP + ilt_y);
    }
}

// ---------------------------------------------------------------------------
// Kernel 4: fused gather + bf16-split GEMM on warp-level mma (HMMA).
// CTA = 128 co x 64 pixels. 256 thr, 8 warps (2 co-halves x 4 pixel-quarters).
#define SM_WHI 0
#define SM_WLO 18432
#define SM_UHI 36864
#define SM_ULO 46080
#define SM_TOTAL 55296
__global__ __launch_bounds__(256, 2) void mma_main_kernel(float* __restrict__ out) {
    extern __shared__ __align__(128) char smem[];
    uint32_t sb = smem_u32(smem);
    int tid = threadIdx.x;
    int wid = tid >> 5, lane = tid & 31;

    int idx = blockIdx.x;
    int b = idx >> 8;
    int h = (idx >> 1) & 127;
    int w0 = (idx & 1) * 64;

    int pixl = tid >> 2;
    int qt = tid & 3;
    int gpix = (b * H + h) * W + w0 + pixl;
    const float4* xb4 = reinterpret_cast<const float4*>(g_xp) + (size_t)b * HP * WP * 32;

    int wm = (wid & 1) * 64;
    int wn = (wid >> 1) * 16;

    int asel = lane >> 3;
    int aRow = ((asel & 1) << 3) + (lane & 7);
    int aK = (asel >> 1) << 3;
    uint32_t aBase = (uint32_t)((wm + aRow) * 144 + aK * 2);
    uint32_t bBase = (uint32_t)((wn + (lane & 7)) * 144 + (((lane >> 3) & 1) << 3) * 2);

    float acc[4][2][4];
#pragma unroll
    for (int mt = 0; mt < 4; ++mt)
#pragma unroll
        for (int nt = 0; nt < 2; ++nt)
#pragma unroll
            for (int j = 0; j < 4; ++j) acc[mt][nt][j] = 0.f;

    for (int chunk = 0; chunk < 18; ++chunk) {
        int n = chunk >> 1, half = chunk & 1;
        __syncthreads();

        // stage weight tiles (linear gmem -> 144B-padded smem rows)
        {
            const float4* ah = reinterpret_cast<const float4*>(g_wA_hi) + chunk * 1024;
            const float4* al = reinterpret_cast<const float4*>(g_wA_lo) + chunk * 1024;
#pragma unroll
            for (int i = 0; i < 4; ++i) {
                int e = tid + i * 256;
                int off = (e >> 3) * 144 + (e & 7) * 16;
                *reinterpret_cast<float4*>(smem + SM_WHI + off) = ah[e];
                *reinterpret_cast<float4*>(smem + SM_WLO + off) = al[e];
            }
        }

        // gather + bf16 split into U tiles ([pix][k] = B^T layout)
        float4 g = g_gates2[n * BHW + gpix];
        int4  o = g_offs2 [n * BHW + gpix];
#pragma unroll
        for (int q = 0; q < 4; ++q) {
            int cb = half * 16 + qt * 4 + q;
            float4 v0 = xb4[(size_t)o.x * 32 + cb];
            float4 v1 = xb4[(size_t)o.y * 32 + cb];
            float4 v2 = xb4[(size_t)o.z * 32 + cb];
            float4 v3 = xb4[(size_t)o.w * 32 + cb];
            float4 v;
            v.x = fmaf(g.w, v3.x, fmaf(g.z, v2.x, fmaf(g.y, v1.x, g.x * v0.x)));
            v.y = fmaf(g.w, v3.y, fmaf(g.z, v2.y, fmaf(g.y, v1.y, g.x * v0.y)));
            v.z = fmaf(g.w, v3.z, fmaf(g.z, v2.z, fmaf(g.y, v1.z, g.x * v0.z)));
            v.w = fmaf(g.w, v3.w, fmaf(g.z, v2.w, fmaf(g.y, v1.w, g.x * v0.w)));

            uint16_t hx, lx, hy, ly, hz, lz, hw_, lw_;
            bf16_split(v.x, hx, lx);
            bf16_split(v.y, hy, ly);
            bf16_split(v.z, hz, lz);
            bf16_split(v.w, hw_, lw_);

            uint32_t uoff = (uint32_t)(pixl * 144 + (qt * 4 + q) * 8);
            *reinterpret_cast<uint32_t*>(smem + SM_UHI + uoff)     = (uint32_t)hx | ((uint32_t)hy << 16);
            *reinterpret_cast<uint32_t*>(smem + SM_UHI + uoff + 4) = (uint32_t)hz | ((uint32_t)hw_ << 16);
            *reinterpret_cast<uint32_t*>(smem + SM_ULO + uoff)     = (uint32_t)lx | ((uint32_t)ly << 16);
            *reinterpret_cast<uint32_t*>(smem + SM_ULO + uoff + 4) = (uint32_t)lz | ((uint32_t)lw_ << 16);
        }
        __syncthreads();

        // HMMA: 4 k-steps of 16
#pragma unroll
        for (int ks = 0; ks < 4; ++ks) {
            uint32_t AH[4][4], AL[4][4];
#pragma unroll
            for (int mt = 0; mt < 4; ++mt) {
                uint32_t ao = aBase + (uint32_t)(mt * 16 * 144 + ks * 32);
                ldmx4(AH[mt], sb + SM_WHI + ao);
                ldmx4(AL[mt], sb + SM_WLO + ao);
            }
#pragma unroll
            for (int nt = 0; nt < 2; ++nt) {
                uint32_t bo = bBase + (uint32_t)(nt * 8 * 144 + ks * 32);
                uint32_t bh0, bh1, bl0, bl1;
                ldmx2(bh0, bh1, sb + SM_UHI + bo);
#pragma unroll
                for (int mt = 0; mt < 4; ++mt) mma_bf16(acc[mt][nt], AH[mt], bh0, bh1);
#pragma unroll
                for (int mt = 0; mt < 4; ++mt) mma_bf16(acc[mt][nt], AL[mt], bh0, bh1);
                ldmx2(bl0, bl1, sb + SM_ULO + bo);
#pragma unroll
                for (int mt = 0; mt < 4; ++mt) mma_bf16(acc[mt][nt], AH[mt], bl0, bl1);
            }
        }
    }

    int g4 = lane >> 2, t4 = lane & 3;
#pragma unroll
    for (int mt = 0; mt < 4; ++mt) {
#pragma unroll
        for (int nt = 0; nt < 2; ++nt) {
            int co = wm + mt * 16 + g4;
            int px = w0 + wn + nt * 8 + t4 * 2;
            float* op = out + (((size_t)b * CO + co) * H + h) * W + px;
            *reinterpret_cast<float2*>(op) = make_float2(acc[mt][nt][0], acc[mt][nt][1]);
            float* op2 = out + (((size_t)b * CO + co + 8) * H + h) * W + px;
            *reinterpret_cast<float2*>(op2) = make_float2(acc[mt][nt][2], acc[mt][nt][3]);
        }
    }
}

// ---------------------------------------------------------------------------
extern "C" void kernel_launch(void* const* d_in, const int* in_sizes, int n_in,
                              void* d_out, int out_size) {
    const float* x      = (const float*)d_in[0];
    const float* w_p    = (const float*)d_in[1];
    const float* b_p    = (const float*)d_in[2];
    const float* w_m    = (const float*)d_in[3];
    const float* b_m    = (const float*)d_in[4];
    const float* w_conv = (const float*)d_in[5];
    float* out = (float*)d_out;

    cudaFuncSetAttribute(mma_main_kernel, cudaFuncAttributeMaxDynamicSharedMemorySize, SM_TOTAL);
    cudaFuncSetAttribute(conv_mma_kernel, cudaFuncAttributeMaxDynamicSharedMemorySize, SC_TOTAL);

    zero_border_kernel<<<(B * 516 * 32 + 255) / 256, 256>>>();
    prep_weights_kernel<<<720, 256>>>(w_p, w_m, w_conv);
    pad_transpose_kernel<<<dim3(W / 32, C / 32, B * H), dim3(32, 8)>>>(x);
    conv_mma_kernel<<<512, 256, SC_TOTAL>>>();
    off_comb_kernel<<<B * H, 128>>>(b_p, b_m);
    mma_main_kernel<<<512, 256, SM_TOTAL>>>(out);
}

// round 7
// speedup vs baseline: 2.6665x; 1.0680x over previous
#include <cuda_runtime.h>
#include <cuda_bf16.h>
#include <math.h>
#include <stdint.h>

// Problem constants
#define B 2
#define C 128
#define H 128
#define W 128
#define HP 130
#define WP 130
#define NPT 9
#define CO 128
#define BHW (B * H * W)

// Scratch (device globals; allocation-free)
__device__ __align__(16) float g_xp[B * HP * WP * C];           // padded NHWC x (~17.3 MB)
__device__ __align__(16) float4 g_gates2[NPT * BHW];            // gates [n][pix] (lt,rb,lb,rt)
__device__ __align__(16) int4   g_offs2 [NPT * BHW];            // corner spatial offsets [n][pix]
__device__ __align__(16) float g_part[27 * BHW];                // offset conv outputs [ch][pix]
// bf16 hi/lo weight tiles, 18 tiles (tap n x ci-half):
//   main conv:   [co 128][k 64]
//   offset conv: [ch 32(27 pad)][k 64]
__device__ __align__(16) unsigned short g_wA_hi[18 * 8192];
__device__ __align__(16) unsigned short g_wA_lo[18 * 8192];
__device__ __align__(16) unsigned short g_wO_hi[18 * 2048];
__device__ __align__(16) unsigned short g_wO_lo[18 * 2048];

// ---------------------------------------------------------------------------
// PTX helpers (all sm_80-era: no arch-"a" gated instructions)
__device__ __forceinline__ uint32_t smem_u32(const void* p) {
    uint32_t a;
    asm("{ .reg .u64 t; cvta.to.shared.u64 t, %1; cvt.u32.u64 %0, t; }" : "=r"(a) : "l"(p));
    return a;
}
__device__ __forceinline__ void ldmx4(uint32_t* r, uint32_t a) {
    asm volatile("ldmatrix.sync.aligned.m8n8.x4.shared.b16 {%0,%1,%2,%3}, [%4];"
                 : "=r"(r[0]), "=r"(r[1]), "=r"(r[2]), "=r"(r[3]) : "r"(a));
}
__device__ __forceinline__ void ldmx2(uint32_t& r0, uint32_t& r1, uint32_t a) {
    asm volatile("ldmatrix.sync.aligned.m8n8.x2.shared.b16 {%0,%1}, [%2];"
                 : "=r"(r0), "=r"(r1) : "r"(a));
}
__device__ __forceinline__ void mma_bf16(float* c, const uint32_t* a, uint32_t b0, uint32_t b1) {
    asm volatile(
        "mma.sync.aligned.m16n8k16.row.col.f32.bf16.bf16.f32 "
        "{%0,%1,%2,%3}, {%4,%5,%6,%7}, {%8,%9}, {%0,%1,%2,%3};"
        : "+f"(c[0]), "+f"(c[1]), "+f"(c[2]), "+f"(c[3])
        : "r"(a[0]), "r"(a[1]), "r"(a[2]), "r"(a[3]), "r"(b0), "r"(b1));
}
__device__ __forceinline__ void bf16_split(float v, uint16_t& hi, uint16_t& lo) {
    __nv_bfloat16 h = __float2bfloat16_rn(v);
    __nv_bfloat16 l = __float2bfloat16_rn(v - __bfloat162float(h));
    hi = __bfloat16_as_ushort(h);
    lo = __bfloat16_as_ushort(l);
}
__device__ __forceinline__ uint32_t pack2(uint16_t a, uint16_t b) {
    return (uint32_t)a | ((uint32_t)b << 16);
}

// ---------------------------------------------------------------------------
// Kernel 0: zero only the pad border of g_xp (interior fully overwritten)
__global__ void zero_border_kernel() {
    int i = blockIdx.x * blockDim.x + threadIdx.x;
    if (i >= B * 516 * 32) return;
    int q = i & 31;
    int p = i >> 5;
    int b = p / 516;
    int r = p - b * 516;
    int hh, ww;
    if (r < 130)      { hh = 0;        ww = r; }
    else if (r < 260) { hh = 129;      ww = r - 130; }
    else if (r < 388) { hh = r - 259;  ww = 0; }
    else              { hh = r - 387;  ww = 129; }
    reinterpret_cast<float4*>(g_xp)[((size_t)(b * HP + hh) * WP + ww) * 32 + q] =
        make_float4(0.f, 0.f, 0.f, 0.f);
}

// ---------------------------------------------------------------------------
// Kernel 1: weight re-layouts -> bf16 hi/lo tiles (main + offset conv)
__global__ void prep_weights_kernel(const float* __restrict__ wp,
                                    const float* __restrict__ wm,
                                    const float* __restrict__ wc) {
    const int n_off = 18 * 32 * 64;          // 36864
    const int n_wa  = 18 * 128 * 64;         // 147456
    for (int e = blockIdx.x * blockDim.x + threadIdx.x; e < n_off + n_wa;
         e += gridDim.x * blockDim.x) {
        if (e < n_off) {
            int tile = e >> 11;
            int r = e & 2047;
            int ch = r >> 6;
            int c = r & 63;
            int n = tile >> 1, half = tile & 1;
            int ci = half * 64 + c;
            float v = 0.f;
            if (ch < 18)      v = wp[(ch * C + ci) * 9 + n];
            else if (ch < 27) v = wm[((ch - 18) * C + ci) * 9 + n];
            uint16_t hi, lo;
            bf16_split(v, hi, lo);
            g_wO_hi[e] = hi;
            g_wO_lo[e] = lo;
        } else {
            int t = e - n_off;
            int tile = t >> 13;
            int r = t & 8191;
            int co = r >> 6;
            int c = r & 63;
            int n = tile >> 1, half = tile & 1;
            int ci = half * 64 + c;
            float v = wc[(co * C + ci) * 9 + n];
            uint16_t hi, lo;
            bf16_split(v, hi, lo);
            g_wA_hi[t] = hi;
            g_wA_lo[t] = lo;
        }
    }
}

// ---------------------------------------------------------------------------
// Kernel 2: pad + transpose NCHW -> padded NHWC
__global__ void pad_transpose_kernel(const float* __restrict__ x) {
    __shared__ float tile[32][33];
    int w0 = blockIdx.x * 32;
    int c0 = blockIdx.y * 32;
    int bh = blockIdx.z;
    int b = bh >> 7, h = bh & 127;
    int tx = threadIdx.x, ty = threadIdx.y;
#pragma unroll
    for (int r = 0; r < 4; ++r) {
        int ci = c0 + ty + r * 8;
        tile[ty + r * 8][tx] = x[(((size_t)b * C + ci) * H + h) * W + w0 + tx];
    }
    __syncthreads();
#pragma unroll
    for (int r = 0; r < 4; ++r) {
        int w = w0 + ty + r * 8;
        g_xp[(((size_t)b * HP + h + 1) * WP + (w + 1)) * C + c0 + tx] = tile[tx][ty + r * 8];
    }
}

// ---------------------------------------------------------------------------
// Kernel 3a: offset/mask conv via HMMA, tap-shift trick:
// stage 3 xp rows x 66 pixels hi/lo ONCE per ci-half; 9 taps = address shifts.
// CTA = 27(32) ch x 64 pixels. 256 thr, 8 warps (2 ch-halves x 4 pixel-quarters).
#define SC_UROW (66 * 144)          // 9504 B per xp row
#define SC_UHI 0                    // 3 rows hi: 28512
#define SC_ULO (3 * SC_UROW)        // 3 rows lo: 28512
#define SC_W   (6 * SC_UROW)        // W double buffer: 2 x (hi 4608 + lo 4608)
#define SC_TOTAL (SC_W + 2 * 9216)  // 75456 B
__global__ __launch_bounds__(256) void conv_mma_kernel() {
    extern __shared__ __align__(128) char smem[];
    uint32_t sb = smem_u32(smem);
    int tid = threadIdx.x;
    int wid = tid >> 5, lane = tid & 31;

    int idx = blockIdx.x;
    int b = idx >> 8;
    int h = (idx >> 1) & 127;
    int w0 = (idx & 1) * 64;

    const float4* xb4 = reinterpret_cast<const float4*>(g_xp) + (size_t)b * HP * WP * 32;

    int wm = (wid & 1) * 16;          // ch half
    int wn = (wid >> 1) * 16;         // pixel quarter

    int asel = lane >> 3;
    int aRow = ((asel & 1) << 3) + (lane & 7);
    int aK = (asel >> 1) << 3;
    uint32_t aBase = (uint32_t)((wm + aRow) * 144 + aK * 2);
    uint32_t bPix = (uint32_t)(wn + (lane & 7));
    uint32_t bKoff = (uint32_t)((((lane >> 3) & 1) << 3) * 2);

    float acc[2][4];
#pragma unroll
    for (int nt = 0; nt < 2; ++nt)
#pragma unroll
        for (int j = 0; j < 4; ++j) acc[nt][j] = 0.f;

    for (int half = 0; half < 2; ++half) {
        __syncthreads();   // previous MMAs done; U buffer reusable
        // stage U: 3 rows x 66 pixels x 16 float4, hi/lo split
        for (int i = tid; i < 3 * 66 * 16; i += 256) {
            int row = i / (66 * 16);
            int rem = i - row * (66 * 16);
            int pix = rem >> 4;
            int q = rem & 15;
            float4 v = xb4[((size_t)(h + row) * WP + (w0 + pix)) * 32 + half * 16 + q];
            uint16_t hx, lx, hy, ly, hz, lz, hw_, lw_;
            bf16_split(v.x, hx, lx);
            bf16_split(v.y, hy, ly);
            bf16_split(v.z, hz, lz);
            bf16_split(v.w, hw_, lw_);
            uint32_t uoff = (uint32_t)(row * SC_UROW + pix * 144 + q * 8);
            *reinterpret_cast<uint2*>(smem + SC_UHI + uoff) = make_uint2(pack2(hx, hy), pack2(hz, hw_));
            *reinterpret_cast<uint2*>(smem + SC_ULO + uoff) = make_uint2(pack2(lx, ly), pack2(lz, lw_));
        }

#pragma unroll
        for (int tap = 0; tap < 9; ++tap) {
            int dh = tap / 3, dw = tap - dh * 3;
            int wb = tap & 1;
            uint32_t wbase = (uint32_t)(SC_W + wb * 9216);
            __syncthreads();   // prev MMA on this W buffer done (or U staged, tap 0)
            {
                int chunk = tap * 2 + half;
                int e = tid;                     // 256 threads, 256 float4 each buf
                int off = (e >> 3) * 144 + (e & 7) * 16;
                *reinterpret_cast<float4*>(smem + wbase + off) =
                    reinterpret_cast<const float4*>(g_wO_hi)[chunk * 256 + e];
                *reinterpret_cast<float4*>(smem + wbase + 4608 + off) =
                    reinterpret_cast<const float4*>(g_wO_lo)[chunk * 256 + e];
            }
            __syncthreads();

            uint32_t ubase = (uint32_t)(dh * SC_UROW) + (bPix + dw) * 144 + bKoff;
#pragma unroll
            for (int ks = 0; ks < 4; ++ks) {
                uint32_t AH[4], AL[4];
                uint32_t ao = wbase + aBase + (uint32_t)(ks * 32);
                ldmx4(AH, sb + ao);
                ldmx4(AL, sb + 4608 + ao);
#pragma unroll
                for (int nt = 0; nt < 2; ++nt) {
                    uint32_t bo = ubase + (uint32_t)(nt * 8 * 144 + ks * 32);
                    uint32_t bh0, bh1, bl0, bl1;
                    ldmx2(bh0, bh1, sb + SC_UHI + bo);
                    mma_bf16(acc[nt], AH, bh0, bh1);
                    mma_bf16(acc[nt], AL, bh0, bh1);
                    ldmx2(bl0, bl1, sb + SC_ULO + bo);
                    mma_bf16(acc[nt], AH, bl0, bl1);
                }
            }
        }
    }

    int g4 = lane >> 2, t4 = lane & 3;
    int pixbase = (b * H + h) * W + w0;
#pragma unroll
    for (int nt = 0; nt < 2; ++nt) {
        int px = wn + nt * 8 + t4 * 2;
        int ch = wm + g4;
        if (ch < 27)
            *reinterpret_cast<float2*>(&g_part[(size_t)ch * BHW + pixbase + px]) =
                make_float2(acc[nt][0], acc[nt][1]);
        if (ch + 8 < 27)
            *reinterpret_cast<float2*>(&g_part[(size_t)(ch + 8) * BHW + pixbase + px]) =
                make_float2(acc[nt][2], acc[nt][3]);
    }
}

// ---------------------------------------------------------------------------
// Kernel 3b: bias + sigmoid + bilinear gate/index precompute (tap-major layout)
__global__ __launch_bounds__(128) void off_comb_kernel(const float* __restrict__ bp,
                                                       const float* __restrict__ bm) {
    int bh = blockIdx.x;
    int b = bh >> 7, h = bh & 127;
    int w = threadIdx.x;
    int pix = bh * 128 + w;

    float acc[27];
#pragma unroll
    for (int ch = 0; ch < 18; ++ch) acc[ch] = bp[ch] + g_part[(size_t)ch * BHW + pix];
#pragma unroll
    for (int ch = 18; ch < 27; ++ch) acc[ch] = bm[ch - 18] + g_part[(size_t)ch * BHW + pix];

#pragma unroll
    for (int n = 0; n < NPT; ++n) {
        float m = 1.f / (1.f + expf(-acc[18 + n]));
        float px = acc[n]     + (float)(h + 1) + (float)(n / 3 - 1);
        float py = acc[9 + n] + (float)(w + 1) + (float)(n % 3 - 1);
        float fx = floorf(px), fy = floorf(py);
        float qltx = fminf(fmaxf(fx,       0.f), 129.f);
        float qlty = fminf(fmaxf(fy,       0.f), 129.f);
        float qrbx = fminf(fmaxf(fx + 1.f, 0.f), 129.f);
        float qrby = fminf(fmaxf(fy + 1.f, 0.f), 129.f);
        float pxc = fminf(fmaxf(px, 0.f), 129.f);
        float pyc = fminf(fmaxf(py, 0.f), 129.f);
        float ax = 1.f + (qltx - pxc);
        float bx = 1.f - (qrbx - pxc);
        float ay = 1.f + (qlty - pyc);
        float by = 1.f - (qrby - pyc);
        int ilt_x = (int)qltx, ilt_y = (int)qlty;
        int irb_x = (int)qrbx, irb_y = (int)qrby;
        g_gates2[n * BHW + pix] = make_float4(ax * ay * m, bx * by * m, ax * by * m, bx * ay * m);
        g_offs2 [n * BHW + pix] = make_int4(ilt_x * WP + ilt_y, irb_x * WP + irb_y,
                                            ilt_x * WP + irb_y, irb_x * WP + ilt_y);
    }
}

// ---------------------------------------------------------------------------
// Kernel 4: fused gather + bf16-split GEMM on warp-level mma (HMMA).
// CTA = 128 co x 64 pixels. 256 thr, 8 warps (2 co-halves x 4 pixel-quarters).
#define SM_WHI 0
#define SM_WLO 18432
#define SM_UHI 36864
#define SM_ULO 46080
#define SM_TOTAL 55296
__global__ __launch_bounds__(256, 2) void mma_main_kernel(float* __restrict__ out) {
    extern __shared__ __align__(128) char smem[];
    uint32_t sb = smem_u32(smem);
    int tid = threadIdx.x;
    int wid = tid >> 5, lane = tid & 31;

    int idx = blockIdx.x;
    int b = idx >> 8;
    int h = (idx >> 1) & 127;
    int w0 = (idx & 1) * 64;

    int pixl = tid >> 2;
    int qt = tid & 3;
    int gpix = (b * H + h) * W + w0 + pixl;
    const float4* xb4 = reinterpret_cast<const float4*>(g_xp) + (size_t)b * HP * WP * 32;

    int wm = (wid & 1) * 64;
    int wn = (wid >> 1) * 16;

    int asel = lane >> 3;
    int aRow = ((asel & 1) << 3) + (lane & 7);
    int aK = (asel >> 1) << 3;
    uint32_t aBase = (uint32_t)((wm + aRow) * 144 + aK * 2);
    uint32_t bBase = (uint32_t)((wn + (lane & 7)) * 144 + (((lane >> 3) & 1) << 3) * 2);

    float acc[4][2][4];
#pragma unroll
    for (int mt = 0; mt < 4; ++mt)
#pragma unroll
        for (int nt = 0; nt < 2; ++nt)
#pragma unroll
            for (int j = 0; j < 4; ++j) acc[mt][nt][j] = 0.f;

    for (int chunk = 0; chunk < 18; ++chunk) {
        int n = chunk >> 1, half = chunk & 1;
        __syncthreads();

        // stage weight tiles (linear gmem -> 144B-padded smem rows)
        {
            const float4* ah = reinterpret_cast<const float4*>(g_wA_hi) + chunk * 1024;
            const float4* al = reinterpret_cast<const float4*>(g_wA_lo) + chunk * 1024;
#pragma unroll
            for (int i = 0; i < 4; ++i) {
                int e = tid + i * 256;
                int off = (e >> 3) * 144 + (e & 7) * 16;
                *reinterpret_cast<float4*>(smem + SM_WHI + off) = ah[e];
                *reinterpret_cast<float4*>(smem + SM_WLO + off) = al[e];
            }
        }

        // gather + bf16 split into U tiles ([pix][k] = B^T layout)
        float4 g = g_gates2[n * BHW + gpix];
        int4  o = g_offs2 [n * BHW + gpix];
#pragma unroll
        for (int q = 0; q < 4; ++q) {
            int cb = half * 16 + qt * 4 + q;
            float4 v0 = xb4[(size_t)o.x * 32 + cb];
            float4 v1 = xb4[(size_t)o.y * 32 + cb];
            float4 v2 = xb4[(size_t)o.z * 32 + cb];
            float4 v3 = xb4[(size_t)o.w * 32 + cb];
            float4 v;
            v.x = fmaf(g.w, v3.x, fmaf(g.z, v2.x, fmaf(g.y, v1.x, g.x * v0.x)));
            v.y = fmaf(g.w, v3.y, fmaf(g.z, v2.y, fmaf(g.y, v1.y, g.x * v0.y)));
            v.z = fmaf(g.w, v3.z, fmaf(g.z, v2.z, fmaf(g.y, v1.z, g.x * v0.z)));
            v.w = fmaf(g.w, v3.w, fmaf(g.z, v2.w, fmaf(g.y, v1.w, g.x * v0.w)));

            uint16_t hx, lx, hy, ly, hz, lz, hw_, lw_;
            bf16_split(v.x, hx, lx);
            bf16_split(v.y, hy, ly);
            bf16_split(v.z, hz, lz);
            bf16_split(v.w, hw_, lw_);

            uint32_t uoff = (uint32_t)(pixl * 144 + (qt * 4 + q) * 8);
            *reinterpret_cast<uint2*>(smem + SM_UHI + uoff) = make_uint2(pack2(hx, hy), pack2(hz, hw_));
            *reinterpret_cast<uint2*>(smem + SM_ULO + uoff) = make_uint2(pack2(lx, ly), pack2(lz, lw_));
        }
        __syncthreads();

        // HMMA: 4 k-steps of 16
#pragma unroll
        for (int ks = 0; ks < 4; ++ks) {
            uint32_t AH[4][4], AL[4][4];
#pragma unroll
            for (int mt = 0; mt < 4; ++mt) {
                uint32_t ao = aBase + (uint32_t)(mt * 16 * 144 + ks * 32);
                ldmx4(AH[mt], sb + SM_WHI + ao);
                ldmx4(AL[mt], sb + SM_WLO + ao);
            }
#pragma unroll
            for (int nt = 0; nt < 2; ++nt) {
                uint32_t bo = bBase + (uint32_t)(nt * 8 * 144 + ks * 32);
                uint32_t bh0, bh1, bl0, bl1;
                ldmx2(bh0, bh1, sb + SM_UHI + bo);
#pragma unroll
                for (int mt = 0; mt < 4; ++mt) mma_bf16(acc[mt][nt], AH[mt], bh0, bh1);
#pragma unroll
                for (int mt = 0; mt < 4; ++mt) mma_bf16(acc[mt][nt], AL[mt], bh0, bh1);
                ldmx2(bl0, bl1, sb + SM_ULO + bo);
#pragma unroll
                for (int mt = 0; mt < 4; ++mt) mma_bf16(acc[mt][nt], AH[mt], bl0, bl1);
            }
        }
    }

    int g4 = lane >> 2, t4 = lane & 3;
#pragma unroll
    for (int mt = 0; mt < 4; ++mt) {
#pragma unroll
        for (int nt = 0; nt < 2; ++nt) {
            int co = wm + mt * 16 + g4;
            int px = w0 + wn + nt * 8 + t4 * 2;
            float* op = out + (((size_t)b * CO + co) * H + h) * W + px;
            *reinterpret_cast<float2*>(op) = make_float2(acc[mt][nt][0], acc[mt][nt][1]);
            float* op2 = out + (((size_t)b * CO + co + 8) * H + h) * W + px;
            *reinterpret_cast<float2*>(op2) = make_float2(acc[mt][nt][2], acc[mt][nt][3]);
        }
    }
}

// ---------------------------------------------------------------------------
extern "C" void kernel_launch(void* const* d_in, const int* in_sizes, int n_in,
                              void* d_out, int out_size) {
    const float* x      = (const float*)d_in[0];
    const float* w_p    = (const float*)d_in[1];
    const float* b_p    = (const float*)d_in[2];
    const float* w_m    = (const float*)d_in[3];
    const float* b_m    = (const float*)d_in[4];
    const float* w_conv = (const float*)d_in[5];
    float* out = (float*)d_out;

    cudaFuncSetAttribute(mma_main_kernel, cudaFuncAttributeMaxDynamicSharedMemorySize, SM_TOTAL);
    cudaFuncSetAttribute(conv_mma_kernel, cudaFuncAttributeMaxDynamicSharedMemorySize, SC_TOTAL);

    zero_border_kernel<<<(B * 516 * 32 + 255) / 256, 256>>>();
    prep_weights_kernel<<<720, 256>>>(w_p, w_m, w_conv);
    pad_transpose_kernel<<<dim3(W / 32, C / 32, B * H), dim3(32, 8)>>>(x);
    conv_mma_kernel<<<512, 256, SC_TOTAL>>>();
    off_comb_kernel<<<B * H, 128>>>(b_p, b_m);
    mma_main_kernel<<<512, 256, SM_TOTAL>>>(out);
}